// round 4
// baseline (speedup 1.0000x reference)
#include <cuda_runtime.h>
#include <cuda_bf16.h>
#include <cstdint>

#define V 50000
#define BDIM 4
#define CIN 128
#define COUT 128
#define KCHEB 4
#define FDIM 512              // B*Cin
#define EMAX 800000

// ---------------- scratch (device globals; allocation-free rule) -------------
__device__ float g_x[KCHEB][(size_t)V * FDIM];

__device__ int   g_hist[V];
__device__ int   g_rowptr[V + 1];
__device__ int   g_cursor[V];
__device__ int   g_col[EMAX];
__device__ float g_val[EMAX];

// pre-transposed, tf32-split weights: [kb][o][c]
__device__ float g_wt_hi[KCHEB * COUT * CIN];
__device__ float g_wt_lo[KCHEB * COUT * CIN];

// ---------------- helpers ------------------------------------------------------
__device__ __forceinline__ float to_tf32(float x) {
    uint32_t r;
    asm("cvt.rna.tf32.f32 %0, %1;" : "=r"(r) : "f"(x));
    return __uint_as_float(r);
}

__device__ __forceinline__ void mma_tf32(float& c0, float& c1, float& c2, float& c3,
                                         uint32_t a0, uint32_t a1, uint32_t a2, uint32_t a3,
                                         uint32_t b0, uint32_t b1) {
    asm volatile(
        "mma.sync.aligned.m16n8k8.row.col.f32.tf32.tf32.f32 "
        "{%0,%1,%2,%3}, {%4,%5,%6,%7}, {%8,%9}, {%0,%1,%2,%3};"
        : "+f"(c0), "+f"(c1), "+f"(c2), "+f"(c3)
        : "r"(a0), "r"(a1), "r"(a2), "r"(a3), "r"(b0), "r"(b1));
}

// ---------------- CSR build --------------------------------------------------
__global__ void zero_hist_kernel() {
    int i = blockIdx.x * blockDim.x + threadIdx.x;
    if (i < V) g_hist[i] = 0;
}

__global__ void hist_kernel(const int* __restrict__ row, int E) {
    int i = blockIdx.x * blockDim.x + threadIdx.x;
    if (i < E) atomicAdd(&g_hist[row[i]], 1);
}

__global__ void scan_kernel() {
    __shared__ int sdata[1024];
    __shared__ int s_carry;
    int tid = threadIdx.x;
    if (tid == 0) { s_carry = 0; g_rowptr[0] = 0; }
    __syncthreads();
    for (int base = 0; base < V; base += 1024) {
        int i = base + tid;
        int val = (i < V) ? g_hist[i] : 0;
        sdata[tid] = val;
        __syncthreads();
        #pragma unroll
        for (int off = 1; off < 1024; off <<= 1) {
            int tmp = (tid >= off) ? sdata[tid - off] : 0;
            __syncthreads();
            sdata[tid] += tmp;
            __syncthreads();
        }
        int inc = sdata[tid] + s_carry;
        if (i < V) {
            g_rowptr[i + 1] = inc;
            g_cursor[i]     = inc - val;
        }
        __syncthreads();
        if (tid == 1023) s_carry = s_carry + sdata[1023];
        __syncthreads();
    }
}

__global__ void scatter_kernel(const int* __restrict__ row,
                               const int* __restrict__ col,
                               const float* __restrict__ val, int E) {
    int i = blockIdx.x * blockDim.x + threadIdx.x;
    if (i < E) {
        int r = row[i];
        int p = atomicAdd(&g_cursor[r], 1);
        g_col[p] = col[i];
        g_val[p] = val[i];
    }
}

// ---------------- transpose: x (B,Cin,V) -> g_x[0] (V, B*Cin) ----------------
__global__ void transpose_kernel(const float* __restrict__ x) {
    __shared__ float tile[32][33];
    int v0 = blockIdx.x * 32;
    int f0 = blockIdx.y * 32;
    int tx = threadIdx.x, ty = threadIdx.y;   // 32 x 8
    #pragma unroll
    for (int r = 0; r < 32; r += 8) {
        int f = f0 + ty + r;
        int v = v0 + tx;
        tile[ty + r][tx] = (v < V) ? x[(size_t)f * V + v] : 0.f;
    }
    __syncthreads();
    #pragma unroll
    for (int r = 0; r < 32; r += 8) {
        int v = v0 + ty + r;
        int f = f0 + tx;
        if (v < V) g_x[0][(size_t)v * FDIM + f] = tile[tx][ty + r];
    }
}

// ---------------- weight prep: W(kb,c,o) -> Wt_hi/lo(kb,o,c) tf32 split ------
__global__ void wprep_kernel(const float* __restrict__ W) {
    int idx = blockIdx.x * blockDim.x + threadIdx.x;
    if (idx >= KCHEB * CIN * COUT) return;
    int o  = idx & 127;
    int c  = (idx >> 7) & 127;
    int kb = idx >> 14;
    float w  = W[idx];
    float hi = to_tf32(w);
    float lo = to_tf32(w - hi);
    int dst = ((kb << 7) + o) * CIN + c;
    g_wt_hi[dst] = hi;
    g_wt_lo[dst] = lo;
}

// ---------------- SpMM + Chebyshev combine -----------------------------------
__global__ void spmm_cheb_kernel(int ii, int pi, int oi,
                                 float alpha, float beta) {
    const float* __restrict__ xin   = &g_x[ii][0];
    const float* __restrict__ xprev = &g_x[pi][0];
    float*       __restrict__ xout  = &g_x[oi][0];

    int gw   = (blockIdx.x * blockDim.x + threadIdx.x) >> 5;
    int lane = threadIdx.x & 31;
    int r  = gw >> 2;
    int ch = gw & 3;
    if (r >= V) return;
    int fo = ch * 128 + (lane << 2);

    int e0 = g_rowptr[r];
    int e1 = g_rowptr[r + 1];

    float4 s = make_float4(0.f, 0.f, 0.f, 0.f);
    for (int e = e0; e < e1; e++) {
        int   c = g_col[e];
        float w = g_val[e];
        float4 xv = *(const float4*)(xin + (size_t)c * FDIM + fo);
        s.x += w * xv.x; s.y += w * xv.y; s.z += w * xv.z; s.w += w * xv.w;
    }
    float4 o;
    if (beta != 0.f) {
        float4 p = *(const float4*)(xprev + (size_t)r * FDIM + fo);
        o.x = alpha * s.x + beta * p.x;
        o.y = alpha * s.y + beta * p.y;
        o.z = alpha * s.z + beta * p.z;
        o.w = alpha * s.w + beta * p.w;
    } else {
        o.x = alpha * s.x; o.y = alpha * s.y; o.z = alpha * s.z; o.w = alpha * s.w;
    }
    *(float4*)(xout + (size_t)r * FDIM + fo) = o;
}

// ---------------- 3xTF32 mma.sync GEMM -----------------------------------------
// out[b,o,v] = sum_{kb,c} g_x[kb][v, b*128+c] * W[kb,c,o] + bias[o]
// CTA: 128 v x 128 o, 256 threads (8 warps in 4x2). K streamed in 16 chunks of 32.
// Fragment-major smem:
//   A: [mt(8)][ks(4)][lane(32)][slot(4)]  -> lds.128 per fragment
//   B: [nt(16)][ks(4)][lane(32)][slot(2)] -> lds.64  per fragment
#define A_FRAG_FLOATS (8 * 4 * 32 * 4)   // 4096
#define B_FRAG_FLOATS (16 * 4 * 32 * 2)  // 4096
#define SM_AHI 0
#define SM_ALO (A_FRAG_FLOATS)
#define SM_BHI (2 * A_FRAG_FLOATS)
#define SM_BLO (2 * A_FRAG_FLOATS + B_FRAG_FLOATS)
#define GEMM_SMEM_FLOATS (2 * A_FRAG_FLOATS + 2 * B_FRAG_FLOATS)   // 16384 floats = 64KB

__global__ void __launch_bounds__(256, 2)
cheb_gemm_mma(const float* __restrict__ bias, float* __restrict__ out) {
    extern __shared__ float smem[];
    float* Ah = smem + SM_AHI;
    float* Al = smem + SM_ALO;
    float* Bh = smem + SM_BHI;
    float* Bl = smem + SM_BLO;

    int t     = threadIdx.x;
    int wid   = t >> 5;
    int lane  = t & 31;
    int mw    = wid & 3;      // warp m index (0..3) -> rows mw*32
    int nw    = wid >> 2;     // warp n index (0..1) -> cols nw*64
    int vbase = blockIdx.x * 128;
    int b     = blockIdx.y;

    // accumulators: [mt2(2)][nt8(8)][4]
    float acc[2][8][4];
    #pragma unroll
    for (int i = 0; i < 2; i++)
        #pragma unroll
        for (int j = 0; j < 8; j++)
            #pragma unroll
            for (int q = 0; q < 4; q++) acc[i][j][q] = 0.f;

    // staging thread mapping: row r = t>>1, quads (t&1)*4 .. +3
    int srow  = t >> 1;
    int qbase = (t & 1) * 4;

    for (int ci = 0; ci < 16; ci++) {
        int kb = ci >> 2;
        int cc = (ci & 3) * 32;

        __syncthreads();   // previous chunk's compute done before overwrite

        // ---- stage A chunk (128 v x 32 c), tf32 hi/lo split, fragment-major
        {
            const float* Asrc = &g_x[kb][0];
            int v = vbase + srow;
            int mt  = srow >> 4;
            int rr  = srow & 15;
            int gid = rr & 7;
            int rslot = rr >> 3;
            #pragma unroll
            for (int qi = 0; qi < 4; qi++) {
                int q = qbase + qi;
                float4 g = make_float4(0.f, 0.f, 0.f, 0.f);
                if (v < V)
                    g = *(const float4*)(Asrc + (size_t)v * FDIM + b * CIN + cc + q * 4);
                int ks   = q >> 1;
                int slot = rslot + 2 * (q & 1);
                int base = ((mt * 4 + ks) * 32 + gid * 4) * 4 + slot;
                float vx[4] = { g.x, g.y, g.z, g.w };
                #pragma unroll
                for (int j = 0; j < 4; j++) {
                    float hi = to_tf32(vx[j]);
                    float lo = to_tf32(vx[j] - hi);
                    Ah[base + j * 4] = hi;
                    Al[base + j * 4] = lo;
                }
            }
        }
        // ---- stage B chunk (128 o x 32 c) from pre-split weights, fragment-major
        {
            int o   = srow;
            int nt  = o >> 3;
            int gid = o & 7;
            const float* wh = g_wt_hi + ((size_t)((kb << 7) + o)) * CIN + cc;
            const float* wl = g_wt_lo + ((size_t)((kb << 7) + o)) * CIN + cc;
            #pragma unroll
            for (int qi = 0; qi < 4; qi++) {
                int q = qbase + qi;
                float4 ghi = *(const float4*)(wh + q * 4);
                float4 glo = *(const float4*)(wl + q * 4);
                int ks   = q >> 1;
                int slot = q & 1;
                int base = ((nt * 4 + ks) * 32 + gid * 4) * 2 + slot;
                float hx[4] = { ghi.x, ghi.y, ghi.z, ghi.w };
                float lx[4] = { glo.x, glo.y, glo.z, glo.w };
                #pragma unroll
                for (int j = 0; j < 4; j++) {
                    Bh[base + j * 2] = hx[j];
                    Bl[base + j * 2] = lx[j];
                }
            }
        }
        __syncthreads();

        // ---- compute: 4 k-steps of k8
        #pragma unroll
        for (int ks = 0; ks < 4; ks++) {
            uint4 ah[2], al[2];
            #pragma unroll
            for (int mt2 = 0; mt2 < 2; mt2++) {
                int mt = mw * 2 + mt2;
                int ofs = ((mt * 4 + ks) * 32 + lane) * 4;
                ah[mt2] = *(const uint4*)(Ah + ofs);
                al[mt2] = *(const uint4*)(Al + ofs);
            }
            #pragma unroll
            for (int nt8 = 0; nt8 < 8; nt8++) {
                int nt = nw * 8 + nt8;
                int ofs = ((nt * 4 + ks) * 32 + lane) * 2;
                uint32_t bh0 = *(const uint32_t*)(Bh + ofs);
                uint32_t bh1 = *(const uint32_t*)(Bh + ofs + 1);
                uint32_t bl0 = *(const uint32_t*)(Bl + ofs);
                uint32_t bl1 = *(const uint32_t*)(Bl + ofs + 1);
                #pragma unroll
                for (int mt2 = 0; mt2 < 2; mt2++) {
                    float* c = acc[mt2][nt8];
                    mma_tf32(c[0], c[1], c[2], c[3],
                             ah[mt2].x, ah[mt2].y, ah[mt2].z, ah[mt2].w, bh0, bh1);
                    mma_tf32(c[0], c[1], c[2], c[3],
                             al[mt2].x, al[mt2].y, al[mt2].z, al[mt2].w, bh0, bh1);
                    mma_tf32(c[0], c[1], c[2], c[3],
                             ah[mt2].x, ah[mt2].y, ah[mt2].z, ah[mt2].w, bl0, bl1);
                }
            }
        }
    }

    // ---- epilogue: direct stores, out[b,o,v] = acc + bias[o]
    int gid  = lane >> 2;
    int tid4 = lane & 3;
    #pragma unroll
    for (int nt8 = 0; nt8 < 8; nt8++) {
        int o0 = nw * 64 + nt8 * 8 + tid4 * 2;
        float bi0 = __ldg(&bias[o0]);
        float bi1 = __ldg(&bias[o0 + 1]);
        #pragma unroll
        for (int mt2 = 0; mt2 < 2; mt2++) {
            int v0 = vbase + mw * 32 + mt2 * 16 + gid;
            const float* c = acc[mt2][nt8];
            if (v0 < V) {
                out[((size_t)b * COUT + o0)     * V + v0] = c[0] + bi0;
                out[((size_t)b * COUT + o0 + 1) * V + v0] = c[1] + bi1;
            }
            if (v0 + 8 < V) {
                out[((size_t)b * COUT + o0)     * V + v0 + 8] = c[2] + bi0;
                out[((size_t)b * COUT + o0 + 1) * V + v0 + 8] = c[3] + bi1;
            }
        }
    }
}

// ---------------- launcher ----------------------------------------------------
extern "C" void kernel_launch(void* const* d_in, const int* in_sizes, int n_in,
                              void* d_out, int out_size) {
    const float* x        = (const float*)d_in[0];
    const int*   edge_row = (const int*)d_in[1];
    const int*   edge_col = (const int*)d_in[2];
    const float* edge_val = (const float*)d_in[3];
    const float* weights  = (const float*)d_in[4];
    const float* biases   = (const float*)d_in[5];
    float*       out      = (float*)d_out;

    int E = in_sizes[1];

    static bool attr_set = false;
    if (!attr_set) {
        cudaFuncSetAttribute(cheb_gemm_mma,
                             cudaFuncAttributeMaxDynamicSharedMemorySize,
                             GEMM_SMEM_FLOATS * sizeof(float));
        attr_set = true;
    }

    // CSR build
    zero_hist_kernel<<<(V + 255) / 256, 256>>>();
    hist_kernel<<<(E + 255) / 256, 256>>>(edge_row, E);
    scan_kernel<<<1, 1024>>>();
    scatter_kernel<<<(E + 255) / 256, 256>>>(edge_row, edge_col, edge_val, E);

    // weight prep (tf32 split + transpose)
    wprep_kernel<<<(KCHEB * CIN * COUT + 255) / 256, 256>>>(weights);

    // transpose x -> g_x[0] (V, 512)
    {
        dim3 gb((V + 31) / 32, FDIM / 32);
        dim3 tb(32, 8);
        transpose_kernel<<<gb, tb>>>(x);
    }

    // Chebyshev recurrence
    {
        int warps  = V * 4;
        int blocks = (warps * 32 + 255) / 256;
        spmm_cheb_kernel<<<blocks, 256>>>(0, 0, 1, 1.f, 0.f);
        spmm_cheb_kernel<<<blocks, 256>>>(1, 0, 2, 2.f, -1.f);
        spmm_cheb_kernel<<<blocks, 256>>>(2, 1, 3, 2.f, -1.f);
    }

    // tensor-core (mma.sync) GEMM + bias + output permute
    {
        dim3 gb((V + 127) / 128, BDIM);
        cheb_gemm_mma<<<gb, 256, GEMM_SMEM_FLOATS * sizeof(float)>>>(biases, out);
    }
}

// round 5
// speedup vs baseline: 1.5839x; 1.5839x over previous
#include <cuda_runtime.h>
#include <cuda_bf16.h>
#include <cstdint>

#define V 50000
#define BDIM 4
#define CIN 128
#define COUT 128
#define KCHEB 4
#define FDIM 512              // B*Cin
#define EMAX 800000

// ---------------- scratch (device globals; allocation-free rule) -------------
__device__ float g_x[KCHEB][(size_t)V * FDIM];

__device__ int   g_hist[V];
__device__ int   g_rowptr[V + 1];
__device__ int   g_cursor[V];
__device__ int   g_col[EMAX];
__device__ float g_val[EMAX];

// W pre-packed in GEMM fragment layout: [kb*4+j][2048] uint2 {hi_u32, lo_u32}
// (bf16x2 pairs, n8k16 B-fragment-major)
__device__ uint2 g_wfrag[KCHEB * 4][2048];

// ---------------- helpers ------------------------------------------------------
__device__ __forceinline__ uint32_t pack_bf16(float a, float b) {
    __nv_bfloat162 t = __floats2bfloat162_rn(a, b);
    return *reinterpret_cast<uint32_t*>(&t);
}

__device__ __forceinline__ void mma_bf16(float& c0, float& c1, float& c2, float& c3,
                                         uint32_t a0, uint32_t a1, uint32_t a2, uint32_t a3,
                                         uint32_t b0, uint32_t b1) {
    asm volatile(
        "mma.sync.aligned.m16n8k16.row.col.f32.bf16.bf16.f32 "
        "{%0,%1,%2,%3}, {%4,%5,%6,%7}, {%8,%9}, {%0,%1,%2,%3};"
        : "+f"(c0), "+f"(c1), "+f"(c2), "+f"(c3)
        : "r"(a0), "r"(a1), "r"(a2), "r"(a3), "r"(b0), "r"(b1));
}

// ---------------- CSR build --------------------------------------------------
__global__ void zero_hist_kernel() {
    int i = blockIdx.x * blockDim.x + threadIdx.x;
    if (i < V) g_hist[i] = 0;
}

__global__ void hist_kernel(const int* __restrict__ row, int E) {
    int i = blockIdx.x * blockDim.x + threadIdx.x;
    if (i < E) atomicAdd(&g_hist[row[i]], 1);
}

// single-block scan, warp-shuffle based (few barriers)
__global__ void scan_kernel() {
    __shared__ int wsum[32];
    __shared__ int s_carry;
    int tid  = threadIdx.x;
    int lane = tid & 31;
    int w    = tid >> 5;
    if (tid == 0) { s_carry = 0; g_rowptr[0] = 0; }
    __syncthreads();
    for (int base = 0; base < V; base += 1024) {
        int i = base + tid;
        int val = (i < V) ? g_hist[i] : 0;
        int s = val;
        #pragma unroll
        for (int off = 1; off < 32; off <<= 1) {
            int n = __shfl_up_sync(0xFFFFFFFFu, s, off);
            if (lane >= off) s += n;
        }
        if (lane == 31) wsum[w] = s;
        __syncthreads();
        if (w == 0) {
            int t2 = wsum[lane];
            #pragma unroll
            for (int off = 1; off < 32; off <<= 1) {
                int n = __shfl_up_sync(0xFFFFFFFFu, t2, off);
                if (lane >= off) t2 += n;
            }
            wsum[lane] = t2;
        }
        __syncthreads();
        int woff = (w > 0) ? wsum[w - 1] : 0;
        int incl = s + woff + s_carry;
        if (i < V) {
            g_rowptr[i + 1] = incl;
            g_cursor[i]     = incl - val;
        }
        __syncthreads();
        if (tid == 1023) s_carry = incl;
        __syncthreads();
    }
}

__global__ void scatter_kernel(const int* __restrict__ row,
                               const int* __restrict__ col,
                               const float* __restrict__ val, int E) {
    int i = blockIdx.x * blockDim.x + threadIdx.x;
    if (i < E) {
        int r = row[i];
        int p = atomicAdd(&g_cursor[r], 1);
        g_col[p] = col[i];
        g_val[p] = val[i];
    }
}

// ---------------- transpose: x (B,Cin,V) -> g_x[0] (V, B*Cin) ----------------
__global__ void transpose_kernel(const float* __restrict__ x) {
    __shared__ float tile[32][33];
    int v0 = blockIdx.x * 32;
    int f0 = blockIdx.y * 32;
    int tx = threadIdx.x, ty = threadIdx.y;   // 32 x 8
    #pragma unroll
    for (int r = 0; r < 32; r += 8) {
        int f = f0 + ty + r;
        int v = v0 + tx;
        tile[ty + r][tx] = (v < V) ? x[(size_t)f * V + v] : 0.f;
    }
    __syncthreads();
    #pragma unroll
    for (int r = 0; r < 32; r += 8) {
        int v = v0 + ty + r;
        int f = f0 + tx;
        if (v < V) g_x[0][(size_t)v * FDIM + f] = tile[tx][ty + r];
    }
}

// ---------------- weight prep: W(kb,c,o) -> bf16-split n8k16 fragment layout --
__global__ void wprep_kernel(const float* __restrict__ W) {
    int idx = blockIdx.x * blockDim.x + threadIdx.x;   // kb(4) x o(128) x c2(64)
    if (idx >= KCHEB * COUT * 64) return;
    int c2 = idx & 63;
    int o  = (idx >> 6) & 127;
    int kb = idx >> 13;
    int c  = c2 * 2;
    float w0 = W[((size_t)(kb * CIN + c))     * COUT + o];
    float w1 = W[((size_t)(kb * CIN + c + 1)) * COUT + o];
    __nv_bfloat162 H = __floats2bfloat162_rn(w0, w1);
    float r0 = w0 - __bfloat162float(H.x);
    float r1 = w1 - __bfloat162float(H.y);
    uint32_t hi = *reinterpret_cast<uint32_t*>(&H);
    uint32_t lo = pack_bf16(r0, r1);

    int j     = c2 >> 4;          // 32-c chunk within kb
    int cr    = c & 31;
    int ks    = cr >> 4;          // k16 step
    int kk    = cr & 15;
    int p     = kk >> 1;          // bf16x2 pair index 0..7
    int gc    = p & 3;
    int slotB = p >> 2;           // b0 vs b1
    int nt    = o >> 3;
    int gn    = o & 7;
    int lane  = gn * 4 + gc;
    int u2idx = ((nt * 2 + ks) * 32 + lane) * 2 + slotB;
    g_wfrag[kb * 4 + j][u2idx] = make_uint2(hi, lo);
}

// ---------------- SpMM + Chebyshev combine -----------------------------------
__global__ void spmm_cheb_kernel(int ii, int pi, int oi,
                                 float alpha, float beta) {
    const float* __restrict__ xin   = &g_x[ii][0];
    const float* __restrict__ xprev = &g_x[pi][0];
    float*       __restrict__ xout  = &g_x[oi][0];

    int gw   = (blockIdx.x * blockDim.x + threadIdx.x) >> 5;
    int lane = threadIdx.x & 31;
    int r  = gw >> 2;
    int ch = gw & 3;
    if (r >= V) return;
    int fo = ch * 128 + (lane << 2);

    int e0 = g_rowptr[r];
    int e1 = g_rowptr[r + 1];

    float4 s = make_float4(0.f, 0.f, 0.f, 0.f);
    for (int e = e0; e < e1; e++) {
        int   c = g_col[e];
        float w = g_val[e];
        float4 xv = *(const float4*)(xin + (size_t)c * FDIM + fo);
        s.x += w * xv.x; s.y += w * xv.y; s.z += w * xv.z; s.w += w * xv.w;
    }
    float4 o;
    if (beta != 0.f) {
        float4 p = *(const float4*)(xprev + (size_t)r * FDIM + fo);
        o.x = alpha * s.x + beta * p.x;
        o.y = alpha * s.y + beta * p.y;
        o.z = alpha * s.z + beta * p.z;
        o.w = alpha * s.w + beta * p.w;
    } else {
        o.x = alpha * s.x; o.y = alpha * s.y; o.z = alpha * s.z; o.w = alpha * s.w;
    }
    *(float4*)(xout + (size_t)r * FDIM + fo) = o;
}

// ---------------- bf16-split mma.sync GEMM -------------------------------------
// out[b,o,v] = sum_{kb,c} g_x[kb][v, b*128+c] * W[kb,c,o] + bias[o]
// CTA: 128 v x 128 o, 256 threads (8 warps 4x2). K streamed in 16 chunks of 32 c.
// Smem fragment-major, (hi,lo) interleaved:
//   A: uint4 AS4[mt(8)][ks(2)][sh(2)][lane(32)]   (16 KB)
//   B: uint4 BS4[nt(16)][ks(2)][lane(32)]          (16 KB)
__global__ void __launch_bounds__(256, 2)
cheb_gemm_mma(const float* __restrict__ bias, float* __restrict__ out) {
    __shared__ uint4 AS4[1024];
    __shared__ uint4 BS4[1024];
    uint2* AS2 = reinterpret_cast<uint2*>(AS4);

    int t     = threadIdx.x;
    int wid   = t >> 5;
    int lane  = t & 31;
    int mw    = wid & 3;      // warp m index -> rows mw*32
    int nw    = wid >> 2;     // warp n index -> cols nw*64
    int vbase = blockIdx.x * 128;
    int b     = blockIdx.y;

    float acc[2][8][4];
    #pragma unroll
    for (int i = 0; i < 2; i++)
        #pragma unroll
        for (int j = 0; j < 8; j++)
            #pragma unroll
            for (int q = 0; q < 4; q++) acc[i][j][q] = 0.f;

    // staging thread mapping
    int par  = t & 1;
    int srow = t >> 1;          // 0..127
    int smt  = srow >> 4;
    int sfr  = srow & 15;
    int sgr  = sfr & 7;
    int shalf = sfr >> 3;
    int v    = vbase + srow;
    // B staging mapping (same srow = o)
    int bnt = srow >> 3;
    // A fragment base for this CTA's source row
    for (int ci = 0; ci < 16; ci++) {
        int kb = ci >> 2;
        int j  = ci & 3;
        int cc = j * 32;

        __syncthreads();   // previous chunk's compute done before overwrite

        // ---- stage A chunk (128 v x 32 c): bf16 hi/lo split, fragment-major
        {
            const float* arow = &g_x[kb][0] + (size_t)v * FDIM + b * CIN + cc;
            #pragma unroll
            for (int qi = 0; qi < 4; qi++) {
                int q = par + 2 * qi;          // 0..7
                float4 g = (v < V) ? *(const float4*)(arow + q * 4)
                                   : make_float4(0.f, 0.f, 0.f, 0.f);
                __nv_bfloat162 H0 = __floats2bfloat162_rn(g.x, g.y);
                __nv_bfloat162 H1 = __floats2bfloat162_rn(g.z, g.w);
                uint32_t h0 = *reinterpret_cast<uint32_t*>(&H0);
                uint32_t h1 = *reinterpret_cast<uint32_t*>(&H1);
                uint32_t l0 = pack_bf16(g.x - __bfloat162float(H0.x),
                                        g.y - __bfloat162float(H0.y));
                uint32_t l1 = pack_bf16(g.z - __bfloat162float(H1.x),
                                        g.w - __bfloat162float(H1.y));
                int ks  = q >> 2;
                int kk4 = (q & 3) * 4;
                int p0  = kk4 >> 1;            // 0,2,4,6
                int gc0 = p0 & 3;              // 0 or 2
                int sh  = p0 >> 2;
                int lane0 = sgr * 4 + gc0;
                int base = ((smt * 2 + ks) * 2 + sh) * 32;
                AS2[(base + lane0) * 2 + shalf]     = make_uint2(h0, l0);
                AS2[(base + lane0 + 1) * 2 + shalf] = make_uint2(h1, l1);
            }
        }
        // ---- stage B chunk: pure copy from pre-fragmented gmem
        {
            const uint4* src = reinterpret_cast<const uint4*>(g_wfrag[kb * 4 + j]);
            #pragma unroll
            for (int s = 0; s < 4; s++)
                BS4[t + s * 256] = src[t + s * 256];
        }
        __syncthreads();

        // ---- compute: 2 k16 steps
        #pragma unroll
        for (int ks = 0; ks < 2; ks++) {
            uint32_t ah[2][4], al[2][4];
            #pragma unroll
            for (int mt2 = 0; mt2 < 2; mt2++) {
                int mt = mw * 2 + mt2;
                uint4 u0 = AS4[((mt * 2 + ks) * 2 + 0) * 32 + lane];
                uint4 u1 = AS4[((mt * 2 + ks) * 2 + 1) * 32 + lane];
                ah[mt2][0] = u0.x; al[mt2][0] = u0.y;
                ah[mt2][1] = u0.z; al[mt2][1] = u0.w;
                ah[mt2][2] = u1.x; al[mt2][2] = u1.y;
                ah[mt2][3] = u1.z; al[mt2][3] = u1.w;
            }
            #pragma unroll
            for (int nt8 = 0; nt8 < 8; nt8++) {
                int nt = nw * 8 + nt8;
                uint4 bu = BS4[(nt * 2 + ks) * 32 + lane];
                // bu = {b0h, b0l, b1h, b1l}
                #pragma unroll
                for (int mt2 = 0; mt2 < 2; mt2++) {
                    float* c = acc[mt2][nt8];
                    mma_bf16(c[0], c[1], c[2], c[3],
                             ah[mt2][0], ah[mt2][1], ah[mt2][2], ah[mt2][3],
                             bu.x, bu.z);
                    mma_bf16(c[0], c[1], c[2], c[3],
                             al[mt2][0], al[mt2][1], al[mt2][2], al[mt2][3],
                             bu.x, bu.z);
                    mma_bf16(c[0], c[1], c[2], c[3],
                             ah[mt2][0], ah[mt2][1], ah[mt2][2], ah[mt2][3],
                             bu.y, bu.w);
                }
            }
        }
    }

    // ---- epilogue: direct stores, out[b,o,v] = acc + bias[o]
    int gid  = lane >> 2;
    int tid4 = lane & 3;
    #pragma unroll
    for (int nt8 = 0; nt8 < 8; nt8++) {
        int o0 = nw * 64 + nt8 * 8 + tid4 * 2;
        float bi0 = __ldg(&bias[o0]);
        float bi1 = __ldg(&bias[o0 + 1]);
        #pragma unroll
        for (int mt2 = 0; mt2 < 2; mt2++) {
            int v0 = vbase + mw * 32 + mt2 * 16 + gid;
            const float* c = acc[mt2][nt8];
            if (v0 < V) {
                out[((size_t)b * COUT + o0)     * V + v0] = c[0] + bi0;
                out[((size_t)b * COUT + o0 + 1) * V + v0] = c[1] + bi1;
            }
            if (v0 + 8 < V) {
                out[((size_t)b * COUT + o0)     * V + v0 + 8] = c[2] + bi0;
                out[((size_t)b * COUT + o0 + 1) * V + v0 + 8] = c[3] + bi1;
            }
        }
    }
}

// ---------------- launcher ----------------------------------------------------
extern "C" void kernel_launch(void* const* d_in, const int* in_sizes, int n_in,
                              void* d_out, int out_size) {
    const float* x        = (const float*)d_in[0];
    const int*   edge_row = (const int*)d_in[1];
    const int*   edge_col = (const int*)d_in[2];
    const float* edge_val = (const float*)d_in[3];
    const float* weights  = (const float*)d_in[4];
    const float* biases   = (const float*)d_in[5];
    float*       out      = (float*)d_out;

    int E = in_sizes[1];

    // CSR build
    zero_hist_kernel<<<(V + 255) / 256, 256>>>();
    hist_kernel<<<(E + 255) / 256, 256>>>(edge_row, E);
    scan_kernel<<<1, 1024>>>();
    scatter_kernel<<<(E + 255) / 256, 256>>>(edge_row, edge_col, edge_val, E);

    // weight prep (bf16 split into fragment layout)
    wprep_kernel<<<(KCHEB * COUT * 64 + 255) / 256, 256>>>(weights);

    // transpose x -> g_x[0] (V, 512)
    {
        dim3 gb((V + 31) / 32, FDIM / 32);
        dim3 tb(32, 8);
        transpose_kernel<<<gb, tb>>>(x);
    }

    // Chebyshev recurrence
    {
        int warps  = V * 4;
        int blocks = (warps * 32 + 255) / 256;
        spmm_cheb_kernel<<<blocks, 256>>>(0, 0, 1, 1.f, 0.f);
        spmm_cheb_kernel<<<blocks, 256>>>(1, 0, 2, 2.f, -1.f);
        spmm_cheb_kernel<<<blocks, 256>>>(2, 1, 3, 2.f, -1.f);
    }

    // tensor-core (mma.sync bf16-split) GEMM + bias + output permute
    {
        dim3 gb((V + 127) / 128, BDIM);
        cheb_gemm_mma<<<gb, 256>>>(biases, out);
    }
}

// round 6
// speedup vs baseline: 1.5908x; 1.0043x over previous
#include <cuda_runtime.h>
#include <cuda_bf16.h>
#include <cstdint>

#define V 50000
#define BDIM 4
#define CIN 128
#define COUT 128
#define KCHEB 4
#define FDIM 512              // B*Cin
#define EMAX 800000

// ---------------- scratch (device globals; allocation-free rule) -------------
__device__ float g_x[KCHEB][(size_t)V * FDIM];

__device__ int   g_hist[V];
__device__ int   g_rowptr[V + 1];
__device__ int   g_cursor[V];
__device__ int   g_col[EMAX];
__device__ float g_val[EMAX];

// W pre-packed in GEMM fragment layout: [kb*4+j][2048] uint2 {hi_u32, lo_u32}
__device__ uint2 g_wfrag[KCHEB * 4][2048];

// ---------------- helpers ------------------------------------------------------
__device__ __forceinline__ uint32_t smem_u32(const void* p) {
    uint32_t a;
    asm("{ .reg .u64 t; cvta.to.shared.u64 t, %1; cvt.u32.u64 %0, t; }" : "=r"(a) : "l"(p));
    return a;
}
__device__ __forceinline__ uint32_t pack_bf16(float a, float b) {
    __nv_bfloat162 t = __floats2bfloat162_rn(a, b);
    return *reinterpret_cast<uint32_t*>(&t);
}
__device__ __forceinline__ void mma_bf16(float& c0, float& c1, float& c2, float& c3,
                                         uint32_t a0, uint32_t a1, uint32_t a2, uint32_t a3,
                                         uint32_t b0, uint32_t b1) {
    asm volatile(
        "mma.sync.aligned.m16n8k16.row.col.f32.bf16.bf16.f32 "
        "{%0,%1,%2,%3}, {%4,%5,%6,%7}, {%8,%9}, {%0,%1,%2,%3};"
        : "+f"(c0), "+f"(c1), "+f"(c2), "+f"(c3)
        : "r"(a0), "r"(a1), "r"(a2), "r"(a3), "r"(b0), "r"(b1));
}
__device__ __forceinline__ void cp_async16(void* sdst, const void* gsrc) {
    uint32_t sa = smem_u32(sdst);
    asm volatile("cp.async.cg.shared.global [%0], [%1], 16;" :: "r"(sa), "l"(gsrc) : "memory");
}
#define CP_COMMIT() asm volatile("cp.async.commit_group;" ::: "memory")
#define CP_WAIT0()  asm volatile("cp.async.wait_group 0;" ::: "memory")

// ---------------- CSR build --------------------------------------------------
__global__ void zero_hist_kernel() {
    int i = blockIdx.x * blockDim.x + threadIdx.x;
    if (i < V) g_hist[i] = 0;
}

__global__ void hist_kernel(const int* __restrict__ row, int E) {
    int i = blockIdx.x * blockDim.x + threadIdx.x;
    if (i < E) atomicAdd(&g_hist[row[i]], 1);
}

// single-block scan, warp-shuffle based
__global__ void scan_kernel() {
    __shared__ int wsum[32];
    __shared__ int s_carry;
    int tid  = threadIdx.x;
    int lane = tid & 31;
    int w    = tid >> 5;
    if (tid == 0) { s_carry = 0; g_rowptr[0] = 0; }
    __syncthreads();
    for (int base = 0; base < V; base += 1024) {
        int i = base + tid;
        int val = (i < V) ? g_hist[i] : 0;
        int s = val;
        #pragma unroll
        for (int off = 1; off < 32; off <<= 1) {
            int n = __shfl_up_sync(0xFFFFFFFFu, s, off);
            if (lane >= off) s += n;
        }
        if (lane == 31) wsum[w] = s;
        __syncthreads();
        if (w == 0) {
            int t2 = wsum[lane];
            #pragma unroll
            for (int off = 1; off < 32; off <<= 1) {
                int n = __shfl_up_sync(0xFFFFFFFFu, t2, off);
                if (lane >= off) t2 += n;
            }
            wsum[lane] = t2;
        }
        __syncthreads();
        int woff = (w > 0) ? wsum[w - 1] : 0;
        int incl = s + woff + s_carry;
        if (i < V) {
            g_rowptr[i + 1] = incl;
            g_cursor[i]     = incl - val;
        }
        __syncthreads();
        if (tid == 1023) s_carry = incl;
        __syncthreads();
    }
}

__global__ void scatter_kernel(const int* __restrict__ row,
                               const int* __restrict__ col,
                               const float* __restrict__ val, int E) {
    int i = blockIdx.x * blockDim.x + threadIdx.x;
    if (i < E) {
        int r = row[i];
        int p = atomicAdd(&g_cursor[r], 1);
        g_col[p] = col[i];
        g_val[p] = val[i];
    }
}

// ---------------- transpose: x (B,Cin,V) -> g_x[0] (V, B*Cin) ----------------
__global__ void transpose_kernel(const float* __restrict__ x) {
    __shared__ float tile[32][33];
    int v0 = blockIdx.x * 32;
    int f0 = blockIdx.y * 32;
    int tx = threadIdx.x, ty = threadIdx.y;   // 32 x 8
    #pragma unroll
    for (int r = 0; r < 32; r += 8) {
        int f = f0 + ty + r;
        int v = v0 + tx;
        tile[ty + r][tx] = (v < V) ? x[(size_t)f * V + v] : 0.f;
    }
    __syncthreads();
    #pragma unroll
    for (int r = 0; r < 32; r += 8) {
        int v = v0 + ty + r;
        int f = f0 + tx;
        if (v < V) g_x[0][(size_t)v * FDIM + f] = tile[tx][ty + r];
    }
}

// ---------------- weight prep: W(kb,c,o) -> bf16-split n8k16 fragment layout --
__global__ void wprep_kernel(const float* __restrict__ W) {
    int idx = blockIdx.x * blockDim.x + threadIdx.x;   // kb(4) x o(128) x c2(64)
    if (idx >= KCHEB * COUT * 64) return;
    int c2 = idx & 63;
    int o  = (idx >> 6) & 127;
    int kb = idx >> 13;
    int c  = c2 * 2;
    float w0 = W[((size_t)(kb * CIN + c))     * COUT + o];
    float w1 = W[((size_t)(kb * CIN + c + 1)) * COUT + o];
    __nv_bfloat162 H = __floats2bfloat162_rn(w0, w1);
    float r0 = w0 - __bfloat162float(H.x);
    float r1 = w1 - __bfloat162float(H.y);
    uint32_t hi = *reinterpret_cast<uint32_t*>(&H);
    uint32_t lo = pack_bf16(r0, r1);

    int j     = c2 >> 4;
    int cr    = c & 31;
    int ks    = cr >> 4;
    int kk    = cr & 15;
    int p     = kk >> 1;
    int gc    = p & 3;
    int slotB = p >> 2;
    int nt    = o >> 3;
    int gn    = o & 7;
    int lane  = gn * 4 + gc;
    int u2idx = ((nt * 2 + ks) * 32 + lane) * 2 + slotB;
    g_wfrag[kb * 4 + j][u2idx] = make_uint2(hi, lo);
}

// ---------------- SpMM + Chebyshev combine -----------------------------------
// chunk-major warp order: all warps of chunk 0 first -> 25.6MB L2 working set.
__global__ void spmm_cheb_kernel(int ii, int pi, int oi,
                                 float alpha, float beta) {
    const float* __restrict__ xin   = &g_x[ii][0];
    const float* __restrict__ xprev = &g_x[pi][0];
    float*       __restrict__ xout  = &g_x[oi][0];

    int w    = blockIdx.x * (blockDim.x >> 5) + (threadIdx.x >> 5);
    int lane = threadIdx.x & 31;
    if (w >= 4 * V) return;
    int ch = w / V;            // chunk-major
    int r  = w - ch * V;
    int fo = ch * 128 + (lane << 2);

    int e0 = g_rowptr[r];
    int e1 = g_rowptr[r + 1];

    float4 s = make_float4(0.f, 0.f, 0.f, 0.f);
    int e = e0;
    for (; e + 1 < e1; e += 2) {
        int   c0 = g_col[e],   c1 = g_col[e + 1];
        float w0 = g_val[e],   w1 = g_val[e + 1];
        float4 x0 = __ldg((const float4*)(xin + (size_t)c0 * FDIM + fo));
        float4 x1 = __ldg((const float4*)(xin + (size_t)c1 * FDIM + fo));
        s.x += w0 * x0.x; s.y += w0 * x0.y; s.z += w0 * x0.z; s.w += w0 * x0.w;
        s.x += w1 * x1.x; s.y += w1 * x1.y; s.z += w1 * x1.z; s.w += w1 * x1.w;
    }
    if (e < e1) {
        int   c0 = g_col[e];
        float w0 = g_val[e];
        float4 x0 = __ldg((const float4*)(xin + (size_t)c0 * FDIM + fo));
        s.x += w0 * x0.x; s.y += w0 * x0.y; s.z += w0 * x0.z; s.w += w0 * x0.w;
    }

    float4 o;
    if (beta != 0.f) {
        float4 p = __ldcs((const float4*)(xprev + (size_t)r * FDIM + fo));
        o.x = alpha * s.x + beta * p.x;
        o.y = alpha * s.y + beta * p.y;
        o.z = alpha * s.z + beta * p.z;
        o.w = alpha * s.w + beta * p.w;
    } else {
        o.x = alpha * s.x; o.y = alpha * s.y; o.z = alpha * s.z; o.w = alpha * s.w;
    }
    __stcs((float4*)(xout + (size_t)r * FDIM + fo), o);
}

// ---------------- bf16-split mma.sync GEMM, 2-stage pipeline -------------------
// Smem (dynamic, 64KB): AS4[2][1024] uint4, BS4[2][1024] uint4
__global__ void __launch_bounds__(256, 2)
cheb_gemm_mma(const float* __restrict__ bias, float* __restrict__ out) {
    extern __shared__ uint4 sm4[];
    uint4* ASb = sm4;           // [2][1024]
    uint4* BSb = sm4 + 2048;    // [2][1024]

    int t     = threadIdx.x;
    int wid   = t >> 5;
    int lane  = t & 31;
    int mw    = wid & 3;
    int nw    = wid >> 2;
    int vbase = blockIdx.x * 128;
    int b     = blockIdx.y;

    float acc[2][8][4];
    #pragma unroll
    for (int i = 0; i < 2; i++)
        #pragma unroll
        for (int j = 0; j < 8; j++)
            #pragma unroll
            for (int q = 0; q < 4; q++) acc[i][j][q] = 0.f;

    // staging thread mapping
    int par   = t & 1;
    int srow  = t >> 1;
    int smt   = srow >> 4;
    int sfr   = srow & 15;
    int sgr   = sfr & 7;
    int shalf = sfr >> 3;
    int v     = vbase + srow;
    bool vok  = (v < V);

    // per-chunk A source address helper: chunk ca -> kb=ca>>2, cc=(ca&3)*32
    auto a_src = [&](int ca) -> const float* {
        int kb = ca >> 2;
        int cc = (ca & 3) * 32;
        return &g_x[kb][0] + (size_t)v * FDIM + b * CIN + cc;
    };

    // STS of A chunk from registers into buffer bufi
    auto sts_A = [&](float4* areg, int bufi) {
        uint2* AS2 = reinterpret_cast<uint2*>(ASb + bufi * 1024);
        #pragma unroll
        for (int qi = 0; qi < 4; qi++) {
            int q = par + 2 * qi;
            float4 g = areg[qi];
            __nv_bfloat162 H0 = __floats2bfloat162_rn(g.x, g.y);
            __nv_bfloat162 H1 = __floats2bfloat162_rn(g.z, g.w);
            uint32_t h0 = *reinterpret_cast<uint32_t*>(&H0);
            uint32_t h1 = *reinterpret_cast<uint32_t*>(&H1);
            uint32_t l0 = pack_bf16(g.x - __bfloat162float(H0.x),
                                    g.y - __bfloat162float(H0.y));
            uint32_t l1 = pack_bf16(g.z - __bfloat162float(H1.x),
                                    g.w - __bfloat162float(H1.y));
            int ks  = q >> 2;
            int p0  = ((q & 3) * 4) >> 1;
            int gc0 = p0 & 3;
            int sh  = p0 >> 2;
            int lane0 = sgr * 4 + gc0;
            int base  = ((smt * 2 + ks) * 2 + sh) * 32;
            AS2[(base + lane0) * 2 + shalf]     = make_uint2(h0, l0);
            AS2[(base + lane0 + 1) * 2 + shalf] = make_uint2(h1, l1);
        }
    };
    auto ldg_A = [&](float4* areg, int ca) {
        const float* arow = a_src(ca);
        #pragma unroll
        for (int qi = 0; qi < 4; qi++) {
            int q = par + 2 * qi;
            areg[qi] = vok ? *(const float4*)(arow + q * 4)
                           : make_float4(0.f, 0.f, 0.f, 0.f);
        }
    };
    auto cp_B = [&](int ca, int bufi) {
        const uint4* src = reinterpret_cast<const uint4*>(g_wfrag[ca]);
        uint4* dst = BSb + bufi * 1024;
        #pragma unroll
        for (int s = 0; s < 4; s++)
            cp_async16(dst + t + s * 256, src + t + s * 256);
        CP_COMMIT();
    };

    // ---- prologue: stage chunk 0, prefetch chunk 1 into regs
    float4 areg[4], areg2[4];
    ldg_A(areg, 0);
    cp_B(0, 0);
    sts_A(areg, 0);
    ldg_A(areg2, 1);

    for (int ci = 0; ci < 16; ci++) {
        int cur = ci & 1;
        CP_WAIT0();          // B(ci) arrived
        __syncthreads();     // staging of (ci) visible; compute(ci-1) done

        if (ci < 15) {
            cp_B(ci + 1, cur ^ 1);
            sts_A(areg2, cur ^ 1);
            if (ci < 14) ldg_A(areg, ci + 2);
            // rotate: areg2 <- areg
            #pragma unroll
            for (int qi = 0; qi < 4; qi++) { float4 tmp = areg[qi]; areg[qi] = areg2[qi]; areg2[qi] = tmp; }
        }

        // ---- compute chunk ci
        uint4* AS4 = ASb + cur * 1024;
        uint4* BS4 = BSb + cur * 1024;
        #pragma unroll
        for (int ks = 0; ks < 2; ks++) {
            uint32_t ah[2][4], al[2][4];
            #pragma unroll
            for (int mt2 = 0; mt2 < 2; mt2++) {
                int mt = mw * 2 + mt2;
                uint4 u0 = AS4[((mt * 2 + ks) * 2 + 0) * 32 + lane];
                uint4 u1 = AS4[((mt * 2 + ks) * 2 + 1) * 32 + lane];
                ah[mt2][0] = u0.x; al[mt2][0] = u0.y;
                ah[mt2][1] = u0.z; al[mt2][1] = u0.w;
                ah[mt2][2] = u1.x; al[mt2][2] = u1.y;
                ah[mt2][3] = u1.z; al[mt2][3] = u1.w;
            }
            #pragma unroll
            for (int nt8 = 0; nt8 < 8; nt8++) {
                int nt = nw * 8 + nt8;
                uint4 bu = BS4[(nt * 2 + ks) * 32 + lane];
                #pragma unroll
                for (int mt2 = 0; mt2 < 2; mt2++) {
                    float* c = acc[mt2][nt8];
                    mma_bf16(c[0], c[1], c[2], c[3],
                             ah[mt2][0], ah[mt2][1], ah[mt2][2], ah[mt2][3],
                             bu.x, bu.z);
                    mma_bf16(c[0], c[1], c[2], c[3],
                             al[mt2][0], al[mt2][1], al[mt2][2], al[mt2][3],
                             bu.x, bu.z);
                    mma_bf16(c[0], c[1], c[2], c[3],
                             ah[mt2][0], ah[mt2][1], ah[mt2][2], ah[mt2][3],
                             bu.y, bu.w);
                }
            }
        }
    }

    // ---- epilogue: direct stores, out[b,o,v] = acc + bias[o]
    int gid  = lane >> 2;
    int tid4 = lane & 3;
    #pragma unroll
    for (int nt8 = 0; nt8 < 8; nt8++) {
        int o0 = nw * 64 + nt8 * 8 + tid4 * 2;
        float bi0 = __ldg(&bias[o0]);
        float bi1 = __ldg(&bias[o0 + 1]);
        #pragma unroll
        for (int mt2 = 0; mt2 < 2; mt2++) {
            int v0 = vbase + mw * 32 + mt2 * 16 + gid;
            const float* c = acc[mt2][nt8];
            if (v0 < V) {
                out[((size_t)b * COUT + o0)     * V + v0] = c[0] + bi0;
                out[((size_t)b * COUT + o0 + 1) * V + v0] = c[1] + bi1;
            }
            if (v0 + 8 < V) {
                out[((size_t)b * COUT + o0)     * V + v0 + 8] = c[2] + bi0;
                out[((size_t)b * COUT + o0 + 1) * V + v0 + 8] = c[3] + bi1;
            }
        }
    }
}

// ---------------- launcher ----------------------------------------------------
extern "C" void kernel_launch(void* const* d_in, const int* in_sizes, int n_in,
                              void* d_out, int out_size) {
    const float* x        = (const float*)d_in[0];
    const int*   edge_row = (const int*)d_in[1];
    const int*   edge_col = (const int*)d_in[2];
    const float* edge_val = (const float*)d_in[3];
    const float* weights  = (const float*)d_in[4];
    const float* biases   = (const float*)d_in[5];
    float*       out      = (float*)d_out;

    int E = in_sizes[1];

    static bool attr_set = false;
    if (!attr_set) {
        cudaFuncSetAttribute(cheb_gemm_mma,
                             cudaFuncAttributeMaxDynamicSharedMemorySize,
                             65536);
        attr_set = true;
    }

    // CSR build
    zero_hist_kernel<<<(V + 255) / 256, 256>>>();
    hist_kernel<<<(E + 255) / 256, 256>>>(edge_row, E);
    scan_kernel<<<1, 1024>>>();
    scatter_kernel<<<(E + 255) / 256, 256>>>(edge_row, edge_col, edge_val, E);

    // weight prep (bf16 split into fragment layout)
    wprep_kernel<<<(KCHEB * COUT * 64 + 255) / 256, 256>>>(weights);

    // transpose x -> g_x[0] (V, 512)
    {
        dim3 gb((V + 31) / 32, FDIM / 32);
        dim3 tb(32, 8);
        transpose_kernel<<<gb, tb>>>(x);
    }

    // Chebyshev recurrence (chunk-major SpMM)
    {
        int warps  = V * 4;
        int blocks = (warps + 7) / 8;   // 8 warps per 256-thread block
        spmm_cheb_kernel<<<blocks, 256>>>(0, 0, 1, 1.f, 0.f);
        spmm_cheb_kernel<<<blocks, 256>>>(1, 0, 2, 2.f, -1.f);
        spmm_cheb_kernel<<<blocks, 256>>>(2, 1, 3, 2.f, -1.f);
    }

    // tensor-core (mma.sync bf16-split) GEMM + bias + output permute
    {
        dim3 gb((V + 127) / 128, BDIM);
        cheb_gemm_mma<<<gb, 256, 65536>>>(biases, out);
    }
}

// round 7
// speedup vs baseline: 2.3344x; 1.4674x over previous
#include <cuda_runtime.h>
#include <cuda_fp16.h>
#include <cstdint>

#define V 50000
#define BDIM 4
#define CIN 128
#define COUT 128
#define KCHEB 4
#define FDIM 512              // B*Cin
#define EMAX 800000

// ---------------- scratch (device globals; allocation-free rule) -------------
// x_k stored in fp16 (halves gather traffic; fp16 eps 2.4e-4 << 1e-3 threshold)
__device__ __half g_x[KCHEB][(size_t)V * FDIM];

__device__ int   g_hist[V];
__device__ int   g_rowptr[V + 1];
__device__ int   g_cursor[V];
__device__ int   g_col[EMAX];
__device__ float g_val[EMAX];

// W pre-packed in GEMM fragment layout: [kb*4+j][2048] uint2 {Wh_h2, Wl_h2}
__device__ uint2 g_wfrag[KCHEB * 4][2048];

// ---------------- helpers ------------------------------------------------------
__device__ __forceinline__ uint32_t smem_u32(const void* p) {
    uint32_t a;
    asm("{ .reg .u64 t; cvta.to.shared.u64 t, %1; cvt.u32.u64 %0, t; }" : "=r"(a) : "l"(p));
    return a;
}
__device__ __forceinline__ void mma_f16(float& c0, float& c1, float& c2, float& c3,
                                        uint32_t a0, uint32_t a1, uint32_t a2, uint32_t a3,
                                        uint32_t b0, uint32_t b1) {
    asm volatile(
        "mma.sync.aligned.m16n8k16.row.col.f32.f16.f16.f32 "
        "{%0,%1,%2,%3}, {%4,%5,%6,%7}, {%8,%9}, {%0,%1,%2,%3};"
        : "+f"(c0), "+f"(c1), "+f"(c2), "+f"(c3)
        : "r"(a0), "r"(a1), "r"(a2), "r"(a3), "r"(b0), "r"(b1));
}
__device__ __forceinline__ void cp_async16(void* sdst, const void* gsrc) {
    uint32_t sa = smem_u32(sdst);
    asm volatile("cp.async.cg.shared.global [%0], [%1], 16;" :: "r"(sa), "l"(gsrc) : "memory");
}
#define CP_COMMIT() asm volatile("cp.async.commit_group;" ::: "memory")
#define CP_WAIT0()  asm volatile("cp.async.wait_group 0;" ::: "memory")

// ---------------- CSR build --------------------------------------------------
__global__ void zero_hist_kernel() {
    int i = blockIdx.x * blockDim.x + threadIdx.x;
    if (i < V) g_hist[i] = 0;
}

__global__ void hist_kernel(const int* __restrict__ row, int E) {
    int i = blockIdx.x * blockDim.x + threadIdx.x;
    if (i < E) atomicAdd(&g_hist[row[i]], 1);
}

__global__ void scan_kernel() {
    __shared__ int wsum[32];
    __shared__ int s_carry;
    int tid  = threadIdx.x;
    int lane = tid & 31;
    int w    = tid >> 5;
    if (tid == 0) { s_carry = 0; g_rowptr[0] = 0; }
    __syncthreads();
    for (int base = 0; base < V; base += 1024) {
        int i = base + tid;
        int val = (i < V) ? g_hist[i] : 0;
        int s = val;
        #pragma unroll
        for (int off = 1; off < 32; off <<= 1) {
            int n = __shfl_up_sync(0xFFFFFFFFu, s, off);
            if (lane >= off) s += n;
        }
        if (lane == 31) wsum[w] = s;
        __syncthreads();
        if (w == 0) {
            int t2 = wsum[lane];
            #pragma unroll
            for (int off = 1; off < 32; off <<= 1) {
                int n = __shfl_up_sync(0xFFFFFFFFu, t2, off);
                if (lane >= off) t2 += n;
            }
            wsum[lane] = t2;
        }
        __syncthreads();
        int woff = (w > 0) ? wsum[w - 1] : 0;
        int incl = s + woff + s_carry;
        if (i < V) {
            g_rowptr[i + 1] = incl;
            g_cursor[i]     = incl - val;
        }
        __syncthreads();
        if (tid == 1023) s_carry = incl;
        __syncthreads();
    }
}

__global__ void scatter_kernel(const int* __restrict__ row,
                               const int* __restrict__ col,
                               const float* __restrict__ val, int E) {
    int i = blockIdx.x * blockDim.x + threadIdx.x;
    if (i < E) {
        int r = row[i];
        int p = atomicAdd(&g_cursor[r], 1);
        g_col[p] = col[i];
        g_val[p] = val[i];
    }
}

// ---------------- transpose: x (B,Cin,V) fp32 -> g_x[0] (V, B*Cin) fp16 -------
__global__ void transpose_kernel(const float* __restrict__ x) {
    __shared__ float tile[32][33];
    int v0 = blockIdx.x * 32;
    int f0 = blockIdx.y * 32;
    int tx = threadIdx.x, ty = threadIdx.y;   // 32 x 8
    #pragma unroll
    for (int r = 0; r < 32; r += 8) {
        int f = f0 + ty + r;
        int v = v0 + tx;
        tile[ty + r][tx] = (v < V) ? x[(size_t)f * V + v] : 0.f;
    }
    __syncthreads();
    #pragma unroll
    for (int r = 0; r < 32; r += 8) {
        int v = v0 + ty + r;
        int f = f0 + tx;
        if (v < V) g_x[0][(size_t)v * FDIM + f] = __float2half_rn(tile[tx][ty + r]);
    }
}

// ---------------- weight prep: W(kb,c,o) -> fp16-split n8k16 fragment layout --
__global__ void wprep_kernel(const float* __restrict__ W) {
    int idx = blockIdx.x * blockDim.x + threadIdx.x;   // kb(4) x o(128) x c2(64)
    if (idx >= KCHEB * COUT * 64) return;
    int c2 = idx & 63;
    int o  = (idx >> 6) & 127;
    int kb = idx >> 13;
    int c  = c2 * 2;
    float w0 = W[((size_t)(kb * CIN + c))     * COUT + o];
    float w1 = W[((size_t)(kb * CIN + c + 1)) * COUT + o];
    __half2 H = __floats2half2_rn(w0, w1);
    float r0 = w0 - __half2float(__low2half(H));
    float r1 = w1 - __half2float(__high2half(H));
    __half2 L = __floats2half2_rn(r0, r1);
    uint32_t hi = *reinterpret_cast<uint32_t*>(&H);
    uint32_t lo = *reinterpret_cast<uint32_t*>(&L);

    int j     = c2 >> 4;
    int cr    = c & 31;
    int ks    = cr >> 4;
    int kk    = cr & 15;
    int p     = kk >> 1;
    int gc    = p & 3;
    int slotB = p >> 2;
    int nt    = o >> 3;
    int gn    = o & 7;
    int lane  = gn * 4 + gc;
    int u2idx = ((nt * 2 + ks) * 32 + lane) * 2 + slotB;
    g_wfrag[kb * 4 + j][u2idx] = make_uint2(hi, lo);
}

// ---------------- SpMM + Chebyshev combine (fp16 storage, fp32 accumulate) ----
__global__ void spmm_cheb_kernel(int ii, int pi, int oi,
                                 float alpha, float beta) {
    const __half* __restrict__ xin   = &g_x[ii][0];
    const __half* __restrict__ xprev = &g_x[pi][0];
    __half*       __restrict__ xout  = &g_x[oi][0];

    int w    = blockIdx.x * (blockDim.x >> 5) + (threadIdx.x >> 5);
    int lane = threadIdx.x & 31;
    if (w >= 4 * V) return;
    int ch = w >> 16 >= 0 ? w / V : 0;   // chunk-major
    ch = w / V;
    int r  = w - ch * V;
    int fo = ch * 128 + (lane << 2);     // half index, 8B aligned

    int e0 = g_rowptr[r];
    int e1 = g_rowptr[r + 1];

    float4 s = make_float4(0.f, 0.f, 0.f, 0.f);
    int e = e0;
    for (; e + 1 < e1; e += 2) {
        int   c0 = g_col[e],   c1 = g_col[e + 1];
        float w0 = g_val[e],   w1 = g_val[e + 1];
        uint2 r0 = __ldg((const uint2*)(xin + (size_t)c0 * FDIM + fo));
        uint2 r1 = __ldg((const uint2*)(xin + (size_t)c1 * FDIM + fo));
        float2 a01 = __half22float2(*reinterpret_cast<__half2*>(&r0.x));
        float2 a23 = __half22float2(*reinterpret_cast<__half2*>(&r0.y));
        float2 b01 = __half22float2(*reinterpret_cast<__half2*>(&r1.x));
        float2 b23 = __half22float2(*reinterpret_cast<__half2*>(&r1.y));
        s.x += w0 * a01.x; s.y += w0 * a01.y; s.z += w0 * a23.x; s.w += w0 * a23.y;
        s.x += w1 * b01.x; s.y += w1 * b01.y; s.z += w1 * b23.x; s.w += w1 * b23.y;
    }
    if (e < e1) {
        int   c0 = g_col[e];
        float w0 = g_val[e];
        uint2 r0 = __ldg((const uint2*)(xin + (size_t)c0 * FDIM + fo));
        float2 a01 = __half22float2(*reinterpret_cast<__half2*>(&r0.x));
        float2 a23 = __half22float2(*reinterpret_cast<__half2*>(&r0.y));
        s.x += w0 * a01.x; s.y += w0 * a01.y; s.z += w0 * a23.x; s.w += w0 * a23.y;
    }

    float4 o;
    if (beta != 0.f) {
        float2 praw = __ldcs((const float2*)(xprev + (size_t)r * FDIM + fo));
        uint32_t pu0 = __float_as_uint(praw.x);
        uint32_t pu1 = __float_as_uint(praw.y);
        float2 p01 = __half22float2(*reinterpret_cast<__half2*>(&pu0));
        float2 p23 = __half22float2(*reinterpret_cast<__half2*>(&pu1));
        o.x = alpha * s.x + beta * p01.x;
        o.y = alpha * s.y + beta * p01.y;
        o.z = alpha * s.z + beta * p23.x;
        o.w = alpha * s.w + beta * p23.y;
    } else {
        o.x = alpha * s.x; o.y = alpha * s.y; o.z = alpha * s.z; o.w = alpha * s.w;
    }
    __half2 o01 = __floats2half2_rn(o.x, o.y);
    __half2 o23 = __floats2half2_rn(o.z, o.w);
    float2 st = make_float2(__uint_as_float(*reinterpret_cast<uint32_t*>(&o01)),
                            __uint_as_float(*reinterpret_cast<uint32_t*>(&o23)));
    __stcs((float2*)(xout + (size_t)r * FDIM + fo), st);
}

// ---------------- fp16 mma.sync GEMM (A single, W 2-term split) ----------------
// Smem (dynamic, 48KB): A[2][512] uint4 (8KB each), B[2][1024] uint4 (16KB each)
__global__ void __launch_bounds__(256, 2)
cheb_gemm_mma(const float* __restrict__ bias, float* __restrict__ out) {
    extern __shared__ uint4 sm4[];
    uint4* ASb = sm4;           // [2][512]
    uint4* BSb = sm4 + 1024;    // [2][1024]

    int t     = threadIdx.x;
    int wid   = t >> 5;
    int lane  = t & 31;
    int mw    = wid & 3;
    int nw    = wid >> 2;
    int vbase = blockIdx.x * 128;
    int b     = blockIdx.y;

    float acc[2][8][4];
    #pragma unroll
    for (int i = 0; i < 2; i++)
        #pragma unroll
        for (int j = 0; j < 8; j++)
            #pragma unroll
            for (int q = 0; q < 4; q++) acc[i][j][q] = 0.f;

    // A staging mapping: thread (srow, par=ks)
    int par   = t & 1;            // ks
    int srow  = t >> 1;           // 0..127
    int smt   = srow >> 4;
    int rr    = srow & 15;
    int sg    = rr & 7;
    int shalf = rr >> 3;
    int v     = vbase + srow;
    bool vok  = (v < V);

    auto ldg_A = [&](uint4* areg, int ca) {
        int kb = ca >> 2;
        int cc = (ca & 3) * 32;
        const __half* arow = &g_x[kb][0] + (size_t)v * FDIM + b * CIN + cc + par * 16;
        if (vok) {
            areg[0] = *(const uint4*)(arow);
            areg[1] = *(const uint4*)(arow + 8);
        } else {
            areg[0] = make_uint4(0, 0, 0, 0);
            areg[1] = make_uint4(0, 0, 0, 0);
        }
    };
    // slots per lane-uint4: s0=(half0,p<4) s1=(half0,p>=4) s2=(half1,p<4) s3=(half1,p>=4)
    // thread writes pairs (p, p+4) -> slots (2*shalf, 2*shalf+1): one STS.64 each
    auto sts_A = [&](uint4* areg, int bufi) {
        uint32_t* AS32 = reinterpret_cast<uint32_t*>(ASb + bufi * 512);
        uint32_t q0[4] = { areg[0].x, areg[0].y, areg[0].z, areg[0].w };
        uint32_t q1[4] = { areg[1].x, areg[1].y, areg[1].z, areg[1].w };
        #pragma unroll
        for (int i = 0; i < 4; i++) {
            int lane_i = sg * 4 + i;
            int word = ((smt * 2 + par) * 32 + lane_i) * 4 + 2 * shalf;
            *(uint2*)(AS32 + word) = make_uint2(q0[i], q1[i]);
        }
    };
    auto cp_B = [&](int ca, int bufi) {
        const uint4* src = reinterpret_cast<const uint4*>(g_wfrag[ca]);
        uint4* dst = BSb + bufi * 1024;
        #pragma unroll
        for (int s = 0; s < 4; s++)
            cp_async16(dst + t + s * 256, src + t + s * 256);
        CP_COMMIT();
    };

    // ---- prologue
    uint4 areg[2], areg2[2];
    ldg_A(areg, 0);
    cp_B(0, 0);
    sts_A(areg, 0);
    ldg_A(areg2, 1);

    for (int ci = 0; ci < 16; ci++) {
        int cur = ci & 1;
        CP_WAIT0();
        __syncthreads();

        if (ci < 15) {
            cp_B(ci + 1, cur ^ 1);
            sts_A(areg2, cur ^ 1);
            if (ci < 14) ldg_A(areg, ci + 2);
            #pragma unroll
            for (int qi = 0; qi < 2; qi++) { uint4 tmp = areg[qi]; areg[qi] = areg2[qi]; areg2[qi] = tmp; }
        }

        uint4* AS4 = ASb + cur * 512;
        uint4* BS4 = BSb + cur * 1024;
        #pragma unroll
        for (int ks = 0; ks < 2; ks++) {
            uint4 au[2];
            #pragma unroll
            for (int mt2 = 0; mt2 < 2; mt2++) {
                int mt = mw * 2 + mt2;
                au[mt2] = AS4[(mt * 2 + ks) * 32 + lane];
            }
            #pragma unroll
            for (int nt8 = 0; nt8 < 8; nt8++) {
                int nt = nw * 8 + nt8;
                uint4 bu = BS4[(nt * 2 + ks) * 32 + lane];  // {b0h, b0l, b1h, b1l}
                #pragma unroll
                for (int mt2 = 0; mt2 < 2; mt2++) {
                    float* c = acc[mt2][nt8];
                    // a0=u.x a1=u.z a2=u.y a3=u.w
                    mma_f16(c[0], c[1], c[2], c[3],
                            au[mt2].x, au[mt2].z, au[mt2].y, au[mt2].w,
                            bu.x, bu.z);
                    mma_f16(c[0], c[1], c[2], c[3],
                            au[mt2].x, au[mt2].z, au[mt2].y, au[mt2].w,
                            bu.y, bu.w);
                }
            }
        }
    }

    // ---- epilogue: direct stores
    int gid  = lane >> 2;
    int tid4 = lane & 3;
    #pragma unroll
    for (int nt8 = 0; nt8 < 8; nt8++) {
        int o0 = nw * 64 + nt8 * 8 + tid4 * 2;
        float bi0 = __ldg(&bias[o0]);
        float bi1 = __ldg(&bias[o0 + 1]);
        #pragma unroll
        for (int mt2 = 0; mt2 < 2; mt2++) {
            int v0 = vbase + mw * 32 + mt2 * 16 + gid;
            const float* c = acc[mt2][nt8];
            if (v0 < V) {
                out[((size_t)b * COUT + o0)     * V + v0] = c[0] + bi0;
                out[((size_t)b * COUT + o0 + 1) * V + v0] = c[1] + bi1;
            }
            if (v0 + 8 < V) {
                out[((size_t)b * COUT + o0)     * V + v0 + 8] = c[2] + bi0;
                out[((size_t)b * COUT + o0 + 1) * V + v0 + 8] = c[3] + bi1;
            }
        }
    }
}

// ---------------- launcher ----------------------------------------------------
extern "C" void kernel_launch(void* const* d_in, const int* in_sizes, int n_in,
                              void* d_out, int out_size) {
    const float* x        = (const float*)d_in[0];
    const int*   edge_row = (const int*)d_in[1];
    const int*   edge_col = (const int*)d_in[2];
    const float* edge_val = (const float*)d_in[3];
    const float* weights  = (const float*)d_in[4];
    const float* biases   = (const float*)d_in[5];
    float*       out      = (float*)d_out;

    int E = in_sizes[1];

    static bool attr_set = false;
    if (!attr_set) {
        cudaFuncSetAttribute(cheb_gemm_mma,
                             cudaFuncAttributeMaxDynamicSharedMemorySize,
                             49152);
        attr_set = true;
    }

    // CSR build
    zero_hist_kernel<<<(V + 255) / 256, 256>>>();
    hist_kernel<<<(E + 255) / 256, 256>>>(edge_row, E);
    scan_kernel<<<1, 1024>>>();
    scatter_kernel<<<(E + 255) / 256, 256>>>(edge_row, edge_col, edge_val, E);

    // weight prep (fp16 split into fragment layout)
    wprep_kernel<<<(KCHEB * COUT * 64 + 255) / 256, 256>>>(weights);

    // transpose x -> g_x[0] (V, 512) fp16
    {
        dim3 gb((V + 31) / 32, FDIM / 32);
        dim3 tb(32, 8);
        transpose_kernel<<<gb, tb>>>(x);
    }

    // Chebyshev recurrence
    {
        int warps  = V * 4;
        int blocks = (warps + 7) / 8;
        spmm_cheb_kernel<<<blocks, 256>>>(0, 0, 1, 1.f, 0.f);
        spmm_cheb_kernel<<<blocks, 256>>>(1, 0, 2, 2.f, -1.f);
        spmm_cheb_kernel<<<blocks, 256>>>(2, 1, 3, 2.f, -1.f);
    }

    // fp16 mma GEMM + bias + output permute
    {
        dim3 gb((V + 127) / 128, BDIM);
        cheb_gemm_mma<<<gb, 256, 49152>>>(biases, out);
    }
}

// round 8
// speedup vs baseline: 2.8346x; 1.2143x over previous
#include <cuda_runtime.h>
#include <cuda_fp16.h>
#include <cstdint>

#define V 50000
#define BDIM 4
#define CIN 128
#define COUT 128
#define KCHEB 4
#define FDIM 512              // B*Cin
#define EMAX 800000

// ---------------- scratch (device globals; allocation-free rule) -------------
__device__ __half g_x[KCHEB][(size_t)V * FDIM];

__device__ int   g_hist[V];
__device__ int   g_rowptr[V + 1];
__device__ int   g_cursor[V];
__device__ int   g_col[EMAX];
__device__ float g_val[EMAX];

// W pre-packed in GEMM fragment layout, single fp16:
// [kb*4+j][ (nt*32+lane)*4 + (ks*2+slotB) ]  (uint32 = half2)
__device__ uint32_t g_wfrag[KCHEB * 4][2048];

// ---------------- helpers ------------------------------------------------------
__device__ __forceinline__ uint32_t smem_u32(const void* p) {
    uint32_t a;
    asm("{ .reg .u64 t; cvta.to.shared.u64 t, %1; cvt.u32.u64 %0, t; }" : "=r"(a) : "l"(p));
    return a;
}
__device__ __forceinline__ void mma_f16(float& c0, float& c1, float& c2, float& c3,
                                        uint32_t a0, uint32_t a1, uint32_t a2, uint32_t a3,
                                        uint32_t b0, uint32_t b1) {
    asm volatile(
        "mma.sync.aligned.m16n8k16.row.col.f32.f16.f16.f32 "
        "{%0,%1,%2,%3}, {%4,%5,%6,%7}, {%8,%9}, {%0,%1,%2,%3};"
        : "+f"(c0), "+f"(c1), "+f"(c2), "+f"(c3)
        : "r"(a0), "r"(a1), "r"(a2), "r"(a3), "r"(b0), "r"(b1));
}
__device__ __forceinline__ void cp_async16(void* sdst, const void* gsrc) {
    uint32_t sa = smem_u32(sdst);
    asm volatile("cp.async.cg.shared.global [%0], [%1], 16;" :: "r"(sa), "l"(gsrc) : "memory");
}
#define CP_COMMIT() asm volatile("cp.async.commit_group;" ::: "memory")
#define CP_WAIT0()  asm volatile("cp.async.wait_group 0;" ::: "memory")

// ---------------- zero hist ----------------------------------------------------
__global__ void zero_hist_kernel() {
    int i = blockIdx.x * blockDim.x + threadIdx.x;
    if (i < V) g_hist[i] = 0;
}

// ---------------- prep1: transpose (x -> g_x[0] fp16) || edge histogram -------
#define TB_X 1563                 // ceil(V/32)
#define TB_Y 16                   // FDIM/32
#define TB_TOTAL (TB_X * TB_Y)
__global__ void prep1_kernel(const float* __restrict__ x,
                             const int* __restrict__ row, int E, int histBlocks) {
    __shared__ float tile[32][33];
    int bid = blockIdx.x;
    if (bid < TB_TOTAL) {
        int bx = bid % TB_X;
        int by = bid / TB_X;
        int v0 = bx * 32;
        int f0 = by * 32;
        int tx = threadIdx.x & 31;
        int ty = threadIdx.x >> 5;   // 0..7
        #pragma unroll
        for (int r = 0; r < 32; r += 8) {
            int f = f0 + ty + r;
            int v = v0 + tx;
            tile[ty + r][tx] = (v < V) ? x[(size_t)f * V + v] : 0.f;
        }
        __syncthreads();
        #pragma unroll
        for (int r = 0; r < 32; r += 8) {
            int v = v0 + ty + r;
            int f = f0 + tx;
            if (v < V) g_x[0][(size_t)v * FDIM + f] = __float2half_rn(tile[tx][ty + r]);
        }
    } else {
        int i = (bid - TB_TOTAL) * blockDim.x + threadIdx.x;
        if (i < E) atomicAdd(&g_hist[row[i]], 1);
    }
}

// ---------------- scan ----------------------------------------------------------
__global__ void scan_kernel() {
    __shared__ int wsum[32];
    __shared__ int s_carry;
    int tid  = threadIdx.x;
    int lane = tid & 31;
    int w    = tid >> 5;
    if (tid == 0) { s_carry = 0; g_rowptr[0] = 0; }
    __syncthreads();
    for (int base = 0; base < V; base += 1024) {
        int i = base + tid;
        int val = (i < V) ? g_hist[i] : 0;
        int s = val;
        #pragma unroll
        for (int off = 1; off < 32; off <<= 1) {
            int n = __shfl_up_sync(0xFFFFFFFFu, s, off);
            if (lane >= off) s += n;
        }
        if (lane == 31) wsum[w] = s;
        __syncthreads();
        if (w == 0) {
            int t2 = wsum[lane];
            #pragma unroll
            for (int off = 1; off < 32; off <<= 1) {
                int n = __shfl_up_sync(0xFFFFFFFFu, t2, off);
                if (lane >= off) t2 += n;
            }
            wsum[lane] = t2;
        }
        __syncthreads();
        int woff = (w > 0) ? wsum[w - 1] : 0;
        int incl = s + woff + s_carry;
        if (i < V) {
            g_rowptr[i + 1] = incl;
            g_cursor[i]     = incl - val;
        }
        __syncthreads();
        if (tid == 1023) s_carry = incl;
        __syncthreads();
    }
}

// ---------------- prep2: scatter || wprep ---------------------------------------
__global__ void prep2_kernel(const int* __restrict__ row,
                             const int* __restrict__ col,
                             const float* __restrict__ val, int E,
                             const float* __restrict__ W, int scatBlocks) {
    int bid = blockIdx.x;
    if (bid < scatBlocks) {
        int i = bid * blockDim.x + threadIdx.x;
        if (i < E) {
            int r = row[i];
            int p = atomicAdd(&g_cursor[r], 1);
            g_col[p] = col[i];
            g_val[p] = val[i];
        }
    } else {
        int idx = (bid - scatBlocks) * blockDim.x + threadIdx.x;  // kb x o x c2
        if (idx >= KCHEB * COUT * 64) return;
        int c2 = idx & 63;
        int o  = (idx >> 6) & 127;
        int kb = idx >> 13;
        int c  = c2 * 2;
        float w0 = W[((size_t)(kb * CIN + c))     * COUT + o];
        float w1 = W[((size_t)(kb * CIN + c + 1)) * COUT + o];
        __half2 H = __floats2half2_rn(w0, w1);
        uint32_t hi = *reinterpret_cast<uint32_t*>(&H);
        int j     = c2 >> 4;
        int cr    = c & 31;
        int ks    = cr >> 4;
        int kk    = cr & 15;
        int p     = kk >> 1;
        int gc    = p & 3;
        int slotB = p >> 2;
        int nt    = o >> 3;
        int gn    = o & 7;
        int lane  = gn * 4 + gc;
        g_wfrag[kb * 4 + j][(nt * 32 + lane) * 4 + ks * 2 + slotB] = hi;
    }
}

// ---------------- SpMM + Chebyshev combine (16B gathers) -----------------------
__global__ void spmm_cheb_kernel(int ii, int pi, int oi,
                                 float alpha, float beta) {
    const __half* __restrict__ xin   = &g_x[ii][0];
    const __half* __restrict__ xprev = &g_x[pi][0];
    __half*       __restrict__ xout  = &g_x[oi][0];

    int w    = blockIdx.x * (blockDim.x >> 5) + (threadIdx.x >> 5);
    int lane = threadIdx.x & 31;
    if (w >= 2 * V) return;
    int ch = w / V;                 // 0 or 1
    int r  = w - ch * V;
    int fo = ch * 256 + (lane << 3);   // half index, 16B aligned

    int e0 = g_rowptr[r];
    int e1 = g_rowptr[r + 1];

    float s0 = 0.f, s1 = 0.f, s2 = 0.f, s3 = 0.f,
          s4 = 0.f, s5 = 0.f, s6 = 0.f, s7 = 0.f;
    int e = e0;
    for (; e + 1 < e1; e += 2) {
        int   c0 = g_col[e],   c1 = g_col[e + 1];
        float w0 = g_val[e],   w1 = g_val[e + 1];
        uint4 ra = __ldg((const uint4*)(xin + (size_t)c0 * FDIM + fo));
        uint4 rb = __ldg((const uint4*)(xin + (size_t)c1 * FDIM + fo));
        float2 a0 = __half22float2(*reinterpret_cast<__half2*>(&ra.x));
        float2 a1 = __half22float2(*reinterpret_cast<__half2*>(&ra.y));
        float2 a2 = __half22float2(*reinterpret_cast<__half2*>(&ra.z));
        float2 a3 = __half22float2(*reinterpret_cast<__half2*>(&ra.w));
        float2 b0 = __half22float2(*reinterpret_cast<__half2*>(&rb.x));
        float2 b1 = __half22float2(*reinterpret_cast<__half2*>(&rb.y));
        float2 b2 = __half22float2(*reinterpret_cast<__half2*>(&rb.z));
        float2 b3 = __half22float2(*reinterpret_cast<__half2*>(&rb.w));
        s0 += w0 * a0.x + w1 * b0.x;  s1 += w0 * a0.y + w1 * b0.y;
        s2 += w0 * a1.x + w1 * b1.x;  s3 += w0 * a1.y + w1 * b1.y;
        s4 += w0 * a2.x + w1 * b2.x;  s5 += w0 * a2.y + w1 * b2.y;
        s6 += w0 * a3.x + w1 * b3.x;  s7 += w0 * a3.y + w1 * b3.y;
    }
    if (e < e1) {
        int   c0 = g_col[e];
        float w0 = g_val[e];
        uint4 ra = __ldg((const uint4*)(xin + (size_t)c0 * FDIM + fo));
        float2 a0 = __half22float2(*reinterpret_cast<__half2*>(&ra.x));
        float2 a1 = __half22float2(*reinterpret_cast<__half2*>(&ra.y));
        float2 a2 = __half22float2(*reinterpret_cast<__half2*>(&ra.z));
        float2 a3 = __half22float2(*reinterpret_cast<__half2*>(&ra.w));
        s0 += w0 * a0.x;  s1 += w0 * a0.y;
        s2 += w0 * a1.x;  s3 += w0 * a1.y;
        s4 += w0 * a2.x;  s5 += w0 * a2.y;
        s6 += w0 * a3.x;  s7 += w0 * a3.y;
    }

    if (beta != 0.f) {
        uint4 pr = __ldcs((const uint4*)(xprev + (size_t)r * FDIM + fo));
        float2 p0 = __half22float2(*reinterpret_cast<__half2*>(&pr.x));
        float2 p1 = __half22float2(*reinterpret_cast<__half2*>(&pr.y));
        float2 p2 = __half22float2(*reinterpret_cast<__half2*>(&pr.z));
        float2 p3 = __half22float2(*reinterpret_cast<__half2*>(&pr.w));
        s0 = alpha * s0 + beta * p0.x;  s1 = alpha * s1 + beta * p0.y;
        s2 = alpha * s2 + beta * p1.x;  s3 = alpha * s3 + beta * p1.y;
        s4 = alpha * s4 + beta * p2.x;  s5 = alpha * s5 + beta * p2.y;
        s6 = alpha * s6 + beta * p3.x;  s7 = alpha * s7 + beta * p3.y;
    } else {
        s0 *= alpha; s1 *= alpha; s2 *= alpha; s3 *= alpha;
        s4 *= alpha; s5 *= alpha; s6 *= alpha; s7 *= alpha;
    }
    __half2 o0 = __floats2half2_rn(s0, s1);
    __half2 o1 = __floats2half2_rn(s2, s3);
    __half2 o2 = __floats2half2_rn(s4, s5);
    __half2 o3 = __floats2half2_rn(s6, s7);
    uint4 st = make_uint4(*reinterpret_cast<uint32_t*>(&o0),
                          *reinterpret_cast<uint32_t*>(&o1),
                          *reinterpret_cast<uint32_t*>(&o2),
                          *reinterpret_cast<uint32_t*>(&o3));
    __stcs((uint4*)(xout + (size_t)r * FDIM + fo), st);
}

// ---------------- fp16 mma.sync GEMM (single W) --------------------------------
// Smem (dynamic, 32KB): A[2][512] uint4 (8KB each), B[2][512] uint4 (8KB each)
__global__ void __launch_bounds__(256, 2)
cheb_gemm_mma(const float* __restrict__ bias, float* __restrict__ out) {
    extern __shared__ uint4 sm4[];
    uint4* ASb = sm4;           // [2][512]
    uint4* BSb = sm4 + 1024;    // [2][512]

    int t     = threadIdx.x;
    int wid   = t >> 5;
    int lane  = t & 31;
    int mw    = wid & 3;
    int nw    = wid >> 2;
    int vbase = blockIdx.x * 128;
    int b     = blockIdx.y;

    float acc[2][8][4];
    #pragma unroll
    for (int i = 0; i < 2; i++)
        #pragma unroll
        for (int j = 0; j < 8; j++)
            #pragma unroll
            for (int q = 0; q < 4; q++) acc[i][j][q] = 0.f;

    // A staging mapping: thread (srow, par=ks)
    int par   = t & 1;
    int srow  = t >> 1;
    int smt   = srow >> 4;
    int rr    = srow & 15;
    int sg    = rr & 7;
    int shalf = rr >> 3;
    int v     = vbase + srow;
    bool vok  = (v < V);

    auto ldg_A = [&](uint4* areg, int ca) {
        int kb = ca >> 2;
        int cc = (ca & 3) * 32;
        const __half* arow = &g_x[kb][0] + (size_t)v * FDIM + b * CIN + cc + par * 16;
        if (vok) {
            areg[0] = *(const uint4*)(arow);
            areg[1] = *(const uint4*)(arow + 8);
        } else {
            areg[0] = make_uint4(0, 0, 0, 0);
            areg[1] = make_uint4(0, 0, 0, 0);
        }
    };
    auto sts_A = [&](uint4* areg, int bufi) {
        uint32_t* AS32 = reinterpret_cast<uint32_t*>(ASb + bufi * 512);
        uint32_t q0[4] = { areg[0].x, areg[0].y, areg[0].z, areg[0].w };
        uint32_t q1[4] = { areg[1].x, areg[1].y, areg[1].z, areg[1].w };
        #pragma unroll
        for (int i = 0; i < 4; i++) {
            int lane_i = sg * 4 + i;
            int word = ((smt * 2 + par) * 32 + lane_i) * 4 + 2 * shalf;
            *(uint2*)(AS32 + word) = make_uint2(q0[i], q1[i]);
        }
    };
    auto cp_B = [&](int ca, int bufi) {
        const uint4* src = reinterpret_cast<const uint4*>(g_wfrag[ca]);
        uint4* dst = BSb + bufi * 512;
        #pragma unroll
        for (int s = 0; s < 2; s++)
            cp_async16(dst + t + s * 256, src + t + s * 256);
        CP_COMMIT();
    };

    // ---- prologue
    uint4 areg[2], areg2[2];
    ldg_A(areg, 0);
    cp_B(0, 0);
    sts_A(areg, 0);
    ldg_A(areg2, 1);

    for (int ci = 0; ci < 16; ci++) {
        int cur = ci & 1;
        CP_WAIT0();
        __syncthreads();

        if (ci < 15) {
            cp_B(ci + 1, cur ^ 1);
            sts_A(areg2, cur ^ 1);
            if (ci < 14) ldg_A(areg, ci + 2);
            #pragma unroll
            for (int qi = 0; qi < 2; qi++) { uint4 tmp = areg[qi]; areg[qi] = areg2[qi]; areg2[qi] = tmp; }
        }

        uint4* AS4 = ASb + cur * 512;
        uint4* BS4 = BSb + cur * 512;

        // load A fragments for both ks
        uint4 au[2][2];
        #pragma unroll
        for (int mt2 = 0; mt2 < 2; mt2++) {
            int mt = mw * 2 + mt2;
            au[mt2][0] = AS4[(mt * 2 + 0) * 32 + lane];
            au[mt2][1] = AS4[(mt * 2 + 1) * 32 + lane];
        }
        #pragma unroll
        for (int nt8 = 0; nt8 < 8; nt8++) {
            int nt = nw * 8 + nt8;
            uint4 bu = BS4[nt * 32 + lane];   // {ks0b0, ks0b1, ks1b0, ks1b1}
            #pragma unroll
            for (int mt2 = 0; mt2 < 2; mt2++) {
                float* c = acc[mt2][nt8];
                mma_f16(c[0], c[1], c[2], c[3],
                        au[mt2][0].x, au[mt2][0].z, au[mt2][0].y, au[mt2][0].w,
                        bu.x, bu.y);
                mma_f16(c[0], c[1], c[2], c[3],
                        au[mt2][1].x, au[mt2][1].z, au[mt2][1].y, au[mt2][1].w,
                        bu.z, bu.w);
            }
        }
    }

    // ---- epilogue: direct stores
    int gid  = lane >> 2;
    int tid4 = lane & 3;
    #pragma unroll
    for (int nt8 = 0; nt8 < 8; nt8++) {
        int o0 = nw * 64 + nt8 * 8 + tid4 * 2;
        float bi0 = __ldg(&bias[o0]);
        float bi1 = __ldg(&bias[o0 + 1]);
        #pragma unroll
        for (int mt2 = 0; mt2 < 2; mt2++) {
            int v0 = vbase + mw * 32 + mt2 * 16 + gid;
            const float* c = acc[mt2][nt8];
            if (v0 < V) {
                out[((size_t)b * COUT + o0)     * V + v0] = c[0] + bi0;
                out[((size_t)b * COUT + o0 + 1) * V + v0] = c[1] + bi1;
            }
            if (v0 + 8 < V) {
                out[((size_t)b * COUT + o0)     * V + v0 + 8] = c[2] + bi0;
                out[((size_t)b * COUT + o0 + 1) * V + v0 + 8] = c[3] + bi1;
            }
        }
    }
}

// ---------------- launcher ----------------------------------------------------
extern "C" void kernel_launch(void* const* d_in, const int* in_sizes, int n_in,
                              void* d_out, int out_size) {
    const float* x        = (const float*)d_in[0];
    const int*   edge_row = (const int*)d_in[1];
    const int*   edge_col = (const int*)d_in[2];
    const float* edge_val = (const float*)d_in[3];
    const float* weights  = (const float*)d_in[4];
    const float* biases   = (const float*)d_in[5];
    float*       out      = (float*)d_out;

    int E = in_sizes[1];

    static bool attr_set = false;
    if (!attr_set) {
        cudaFuncSetAttribute(cheb_gemm_mma,
                             cudaFuncAttributeMaxDynamicSharedMemorySize,
                             32768);
        attr_set = true;
    }

    int histBlocks = (E + 255) / 256;
    int wprepBlocks = (KCHEB * COUT * 64 + 255) / 256;

    zero_hist_kernel<<<(V + 255) / 256, 256>>>();
    prep1_kernel<<<TB_TOTAL + histBlocks, 256>>>(x, edge_row, E, histBlocks);
    scan_kernel<<<1, 1024>>>();
    prep2_kernel<<<histBlocks + wprepBlocks, 256>>>(edge_row, edge_col, edge_val, E,
                                                    weights, histBlocks);

    // Chebyshev recurrence
    {
        int warps  = 2 * V;
        int blocks = (warps + 7) / 8;
        spmm_cheb_kernel<<<blocks, 256>>>(0, 0, 1, 1.f, 0.f);
        spmm_cheb_kernel<<<blocks, 256>>>(1, 0, 2, 2.f, -1.f);
        spmm_cheb_kernel<<<blocks, 256>>>(2, 1, 3, 2.f, -1.f);
    }

    // fp16 mma GEMM + bias + output permute
    {
        dim3 gb((V + 127) / 128, BDIM);
        cheb_gemm_mma<<<gb, 256, 32768>>>(biases, out);
    }
}

// round 9
// speedup vs baseline: 3.0731x; 1.0841x over previous
#include <cuda_runtime.h>
#include <cuda_fp16.h>
#include <cstdint>

#define V 50000
#define VPAD 53248            // V rounded up to 4096-multiple for int4 scan
#define BDIM 4
#define CIN 128
#define COUT 128
#define KCHEB 4
#define FDIM 512              // B*Cin
#define EMAX 800000

// ---------------- scratch (device globals; allocation-free rule) -------------
__device__ __half g_x[KCHEB][(size_t)V * FDIM];

__device__ __align__(16) int g_hist[VPAD];
__device__ int   g_rowptr[V + 1];
__device__ int   g_cursor[V];
__device__ int   g_col[EMAX];
__device__ float g_val[EMAX];

// W pre-packed in GEMM fragment layout, single fp16:
// [kb*4+j][ (nt*32+lane)*4 + (ks*2+slotB) ]  (uint32 = half2)
__device__ uint32_t g_wfrag[KCHEB * 4][2048];

// ---------------- helpers ------------------------------------------------------
__device__ __forceinline__ uint32_t smem_u32(const void* p) {
    uint32_t a;
    asm("{ .reg .u64 t; cvta.to.shared.u64 t, %1; cvt.u32.u64 %0, t; }" : "=r"(a) : "l"(p));
    return a;
}
__device__ __forceinline__ void mma_f16(float& c0, float& c1, float& c2, float& c3,
                                        uint32_t a0, uint32_t a1, uint32_t a2, uint32_t a3,
                                        uint32_t b0, uint32_t b1) {
    asm volatile(
        "mma.sync.aligned.m16n8k16.row.col.f32.f16.f16.f32 "
        "{%0,%1,%2,%3}, {%4,%5,%6,%7}, {%8,%9}, {%0,%1,%2,%3};"
        : "+f"(c0), "+f"(c1), "+f"(c2), "+f"(c3)
        : "r"(a0), "r"(a1), "r"(a2), "r"(a3), "r"(b0), "r"(b1));
}
__device__ __forceinline__ void cp_async16(void* sdst, const void* gsrc) {
    uint32_t sa = smem_u32(sdst);
    asm volatile("cp.async.cg.shared.global [%0], [%1], 16;" :: "r"(sa), "l"(gsrc) : "memory");
}
#define CP_COMMIT() asm volatile("cp.async.commit_group;" ::: "memory")
#define CP_WAIT0()  asm volatile("cp.async.wait_group 0;" ::: "memory")

// ---------------- zero hist ----------------------------------------------------
__global__ void zero_hist_kernel() {
    int i = blockIdx.x * blockDim.x + threadIdx.x;
    if (i < VPAD) g_hist[i] = 0;
}

// ---------------- prep1: transpose (x -> g_x[0] fp16) || edge histogram -------
#define TB_X 1563                 // ceil(V/32)
#define TB_Y 8                    // FDIM/64
#define TB_TOTAL (TB_X * TB_Y)
__global__ void prep1_kernel(const float* __restrict__ x,
                             const int* __restrict__ row, int E) {
    __shared__ float tile[64][33];
    int bid = blockIdx.x;
    int t   = threadIdx.x;
    if (bid < TB_TOTAL) {
        int bx = bid % TB_X;
        int by = bid / TB_X;
        int v0 = bx * 32;
        int f0 = by * 64;
        int tx = t & 31;
        int ty = t >> 5;                 // 0..7
        #pragma unroll
        for (int r = 0; r < 8; r++) {
            int fl = ty * 8 + r;         // 0..63
            int v  = v0 + tx;
            tile[fl][tx] = (v < V) ? x[(size_t)(f0 + fl) * V + v] : 0.f;
        }
        __syncthreads();
        int vq = t >> 3;                 // 0..31
        int fq = t & 7;                  // 0..7
        int v  = v0 + vq;
        if (v < V) {
            __half hbuf[8];
            #pragma unroll
            for (int j = 0; j < 8; j++)
                hbuf[j] = __float2half_rn(tile[fq * 8 + j][vq]);
            *(uint4*)(&g_x[0][(size_t)v * FDIM + f0 + fq * 8]) = *(uint4*)hbuf;
        }
    } else {
        int i = (bid - TB_TOTAL) * blockDim.x + t;
        if (i < E) atomicAdd(&g_hist[row[i]], 1);
    }
}

// ---------------- scan: 4 elems/thread, 13 iterations ---------------------------
__global__ void scan_kernel() {
    __shared__ int wsum[32];
    __shared__ int s_carry;
    int tid  = threadIdx.x;
    int lane = tid & 31;
    int w    = tid >> 5;
    if (tid == 0) { s_carry = 0; g_rowptr[0] = 0; }
    __syncthreads();
    for (int base = 0; base < V; base += 4096) {
        int i0 = base + tid * 4;                 // < VPAD always
        int4 h4 = *(const int4*)&g_hist[i0];
        int h[4] = { h4.x, h4.y, h4.z, h4.w };
        int tsum = h[0] + h[1] + h[2] + h[3];
        int s = tsum;
        #pragma unroll
        for (int off = 1; off < 32; off <<= 1) {
            int n = __shfl_up_sync(0xFFFFFFFFu, s, off);
            if (lane >= off) s += n;
        }
        if (lane == 31) wsum[w] = s;
        __syncthreads();
        if (w == 0) {
            int t2 = wsum[lane];
            #pragma unroll
            for (int off = 1; off < 32; off <<= 1) {
                int n = __shfl_up_sync(0xFFFFFFFFu, t2, off);
                if (lane >= off) t2 += n;
            }
            wsum[lane] = t2;
        }
        __syncthreads();
        int c    = s_carry;
        int excl = s - tsum + ((w > 0) ? wsum[w - 1] : 0) + c;
        int run  = excl;
        #pragma unroll
        for (int j = 0; j < 4; j++) {
            int idx = i0 + j;
            if (idx < V) {
                g_cursor[idx] = run;
                run += h[j];
                g_rowptr[idx + 1] = run;
            }
        }
        int total = wsum[31];
        __syncthreads();
        if (tid == 0) s_carry = c + total;
        __syncthreads();
    }
}

// ---------------- prep2: scatter || wprep ---------------------------------------
__global__ void prep2_kernel(const int* __restrict__ row,
                             const int* __restrict__ col,
                             const float* __restrict__ val, int E,
                             const float* __restrict__ W, int scatBlocks) {
    int bid = blockIdx.x;
    if (bid < scatBlocks) {
        int i = bid * blockDim.x + threadIdx.x;
        if (i < E) {
            int r = row[i];
            int p = atomicAdd(&g_cursor[r], 1);
            g_col[p] = col[i];
            g_val[p] = val[i];
        }
    } else {
        int idx = (bid - scatBlocks) * blockDim.x + threadIdx.x;  // kb x o x c2
        if (idx >= KCHEB * COUT * 64) return;
        int c2 = idx & 63;
        int o  = (idx >> 6) & 127;
        int kb = idx >> 13;
        int c  = c2 * 2;
        float w0 = W[((size_t)(kb * CIN + c))     * COUT + o];
        float w1 = W[((size_t)(kb * CIN + c + 1)) * COUT + o];
        __half2 H = __floats2half2_rn(w0, w1);
        uint32_t hi = *reinterpret_cast<uint32_t*>(&H);
        int j     = c2 >> 4;
        int cr    = c & 31;
        int ks    = cr >> 4;
        int kk    = cr & 15;
        int p     = kk >> 1;
        int gc    = p & 3;
        int slotB = p >> 2;
        int nt    = o >> 3;
        int gn    = o & 7;
        int lane  = gn * 4 + gc;
        g_wfrag[kb * 4 + j][(nt * 32 + lane) * 4 + ks * 2 + slotB] = hi;
    }
}

// ---------------- SpMM + Chebyshev combine (16B gathers, 4-edge unroll) --------
__global__ void spmm_cheb_kernel(int ii, int pi, int oi,
                                 float alpha, float beta) {
    const __half* __restrict__ xin   = &g_x[ii][0];
    const __half* __restrict__ xprev = &g_x[pi][0];
    __half*       __restrict__ xout  = &g_x[oi][0];

    int r    = blockIdx.x * (blockDim.x >> 5) + (threadIdx.x >> 5);
    int lane = threadIdx.x & 31;
    if (r >= V) return;
    int fo = (int)blockIdx.y * 256 + (lane << 3);   // half index, 16B aligned

    int e0 = g_rowptr[r];
    int e1 = g_rowptr[r + 1];

    float s0 = 0.f, s1 = 0.f, s2 = 0.f, s3 = 0.f,
          s4 = 0.f, s5 = 0.f, s6 = 0.f, s7 = 0.f;

    auto acc_row = [&](uint4 ra, float wv) {
        float2 a0 = __half22float2(*reinterpret_cast<__half2*>(&ra.x));
        float2 a1 = __half22float2(*reinterpret_cast<__half2*>(&ra.y));
        float2 a2 = __half22float2(*reinterpret_cast<__half2*>(&ra.z));
        float2 a3 = __half22float2(*reinterpret_cast<__half2*>(&ra.w));
        s0 += wv * a0.x;  s1 += wv * a0.y;
        s2 += wv * a1.x;  s3 += wv * a1.y;
        s4 += wv * a2.x;  s5 += wv * a2.y;
        s6 += wv * a3.x;  s7 += wv * a3.y;
    };

    int e = e0;
    for (; e + 3 < e1; e += 4) {
        int   c0 = g_col[e],     c1 = g_col[e + 1];
        int   c2 = g_col[e + 2], c3 = g_col[e + 3];
        float w0 = g_val[e],     w1 = g_val[e + 1];
        float w2 = g_val[e + 2], w3 = g_val[e + 3];
        uint4 ra = __ldg((const uint4*)(xin + (size_t)c0 * FDIM + fo));
        uint4 rb = __ldg((const uint4*)(xin + (size_t)c1 * FDIM + fo));
        uint4 rc = __ldg((const uint4*)(xin + (size_t)c2 * FDIM + fo));
        uint4 rd = __ldg((const uint4*)(xin + (size_t)c3 * FDIM + fo));
        acc_row(ra, w0); acc_row(rb, w1); acc_row(rc, w2); acc_row(rd, w3);
    }
    for (; e < e1; e++) {
        int   c0 = g_col[e];
        float w0 = g_val[e];
        uint4 ra = __ldg((const uint4*)(xin + (size_t)c0 * FDIM + fo));
        acc_row(ra, w0);
    }

    if (beta != 0.f) {
        uint4 pr = __ldcs((const uint4*)(xprev + (size_t)r * FDIM + fo));
        float2 p0 = __half22float2(*reinterpret_cast<__half2*>(&pr.x));
        float2 p1 = __half22float2(*reinterpret_cast<__half2*>(&pr.y));
        float2 p2 = __half22float2(*reinterpret_cast<__half2*>(&pr.z));
        float2 p3 = __half22float2(*reinterpret_cast<__half2*>(&pr.w));
        s0 = alpha * s0 + beta * p0.x;  s1 = alpha * s1 + beta * p0.y;
        s2 = alpha * s2 + beta * p1.x;  s3 = alpha * s3 + beta * p1.y;
        s4 = alpha * s4 + beta * p2.x;  s5 = alpha * s5 + beta * p2.y;
        s6 = alpha * s6 + beta * p3.x;  s7 = alpha * s7 + beta * p3.y;
    } else {
        s0 *= alpha; s1 *= alpha; s2 *= alpha; s3 *= alpha;
        s4 *= alpha; s5 *= alpha; s6 *= alpha; s7 *= alpha;
    }
    __half2 o0 = __floats2half2_rn(s0, s1);
    __half2 o1 = __floats2half2_rn(s2, s3);
    __half2 o2 = __floats2half2_rn(s4, s5);
    __half2 o3 = __floats2half2_rn(s6, s7);
    uint4 st = make_uint4(*reinterpret_cast<uint32_t*>(&o0),
                          *reinterpret_cast<uint32_t*>(&o1),
                          *reinterpret_cast<uint32_t*>(&o2),
                          *reinterpret_cast<uint32_t*>(&o3));
    __stcs((uint4*)(xout + (size_t)r * FDIM + fo), st);
}

// ---------------- fp16 mma.sync GEMM (single W) --------------------------------
// Smem (dynamic, 32KB): A[2][512] uint4 (8KB each), B[2][512] uint4 (8KB each)
__global__ void __launch_bounds__(256, 2)
cheb_gemm_mma(const float* __restrict__ bias, float* __restrict__ out) {
    extern __shared__ uint4 sm4[];
    uint4* ASb = sm4;           // [2][512]
    uint4* BSb = sm4 + 1024;    // [2][512]

    int t     = threadIdx.x;
    int wid   = t >> 5;
    int lane  = t & 31;
    int mw    = wid & 3;
    int nw    = wid >> 2;
    int vbase = blockIdx.x * 128;
    int b     = blockIdx.y;

    float acc[2][8][4];
    #pragma unroll
    for (int i = 0; i < 2; i++)
        #pragma unroll
        for (int j = 0; j < 8; j++)
            #pragma unroll
            for (int q = 0; q < 4; q++) acc[i][j][q] = 0.f;

    // A staging mapping: thread (srow, par=ks)
    int par   = t & 1;
    int srow  = t >> 1;
    int smt   = srow >> 4;
    int rr    = srow & 15;
    int sg    = rr & 7;
    int shalf = rr >> 3;
    int v     = vbase + srow;
    bool vok  = (v < V);

    auto ldg_A = [&](uint4* areg, int ca) {
        int kb = ca >> 2;
        int cc = (ca & 3) * 32;
        const __half* arow = &g_x[kb][0] + (size_t)v * FDIM + b * CIN + cc + par * 16;
        if (vok) {
            areg[0] = *(const uint4*)(arow);
            areg[1] = *(const uint4*)(arow + 8);
        } else {
            areg[0] = make_uint4(0, 0, 0, 0);
            areg[1] = make_uint4(0, 0, 0, 0);
        }
    };
    auto sts_A = [&](uint4* areg, int bufi) {
        uint32_t* AS32 = reinterpret_cast<uint32_t*>(ASb + bufi * 512);
        uint32_t q0[4] = { areg[0].x, areg[0].y, areg[0].z, areg[0].w };
        uint32_t q1[4] = { areg[1].x, areg[1].y, areg[1].z, areg[1].w };
        #pragma unroll
        for (int i = 0; i < 4; i++) {
            int lane_i = sg * 4 + i;
            int word = ((smt * 2 + par) * 32 + lane_i) * 4 + 2 * shalf;
            *(uint2*)(AS32 + word) = make_uint2(q0[i], q1[i]);
        }
    };
    auto cp_B = [&](int ca, int bufi) {
        const uint4* src = reinterpret_cast<const uint4*>(g_wfrag[ca]);
        uint4* dst = BSb + bufi * 512;
        #pragma unroll
        for (int s = 0; s < 2; s++)
            cp_async16(dst + t + s * 256, src + t + s * 256);
        CP_COMMIT();
    };

    // ---- prologue
    uint4 areg[2], areg2[2];
    ldg_A(areg, 0);
    cp_B(0, 0);
    sts_A(areg, 0);
    ldg_A(areg2, 1);

    for (int ci = 0; ci < 16; ci++) {
        int cur = ci & 1;
        CP_WAIT0();
        __syncthreads();

        if (ci < 15) {
            cp_B(ci + 1, cur ^ 1);
            sts_A(areg2, cur ^ 1);
            if (ci < 14) ldg_A(areg, ci + 2);
            #pragma unroll
            for (int qi = 0; qi < 2; qi++) { uint4 tmp = areg[qi]; areg[qi] = areg2[qi]; areg2[qi] = tmp; }
        }

        uint4* AS4 = ASb + cur * 512;
        uint4* BS4 = BSb + cur * 512;

        uint4 au[2][2];
        #pragma unroll
        for (int mt2 = 0; mt2 < 2; mt2++) {
            int mt = mw * 2 + mt2;
            au[mt2][0] = AS4[(mt * 2 + 0) * 32 + lane];
            au[mt2][1] = AS4[(mt * 2 + 1) * 32 + lane];
        }
        #pragma unroll
        for (int nt8 = 0; nt8 < 8; nt8++) {
            int nt = nw * 8 + nt8;
            uint4 bu = BS4[nt * 32 + lane];   // {ks0b0, ks0b1, ks1b0, ks1b1}
            #pragma unroll
            for (int mt2 = 0; mt2 < 2; mt2++) {
                float* c = acc[mt2][nt8];
                mma_f16(c[0], c[1], c[2], c[3],
                        au[mt2][0].x, au[mt2][0].z, au[mt2][0].y, au[mt2][0].w,
                        bu.x, bu.y);
                mma_f16(c[0], c[1], c[2], c[3],
                        au[mt2][1].x, au[mt2][1].z, au[mt2][1].y, au[mt2][1].w,
                        bu.z, bu.w);
            }
        }
    }

    // ---- epilogue: streaming stores
    int gid  = lane >> 2;
    int tid4 = lane & 3;
    #pragma unroll
    for (int nt8 = 0; nt8 < 8; nt8++) {
        int o0 = nw * 64 + nt8 * 8 + tid4 * 2;
        float bi0 = __ldg(&bias[o0]);
        float bi1 = __ldg(&bias[o0 + 1]);
        #pragma unroll
        for (int mt2 = 0; mt2 < 2; mt2++) {
            int v0 = vbase + mw * 32 + mt2 * 16 + gid;
            const float* c = acc[mt2][nt8];
            if (v0 < V) {
                __stcs(&out[((size_t)b * COUT + o0)     * V + v0], c[0] + bi0);
                __stcs(&out[((size_t)b * COUT + o0 + 1) * V + v0], c[1] + bi1);
            }
            if (v0 + 8 < V) {
                __stcs(&out[((size_t)b * COUT + o0)     * V + v0 + 8], c[2] + bi0);
                __stcs(&out[((size_t)b * COUT + o0 + 1) * V + v0 + 8], c[3] + bi1);
            }
        }
    }
}

// ---------------- launcher ----------------------------------------------------
extern "C" void kernel_launch(void* const* d_in, const int* in_sizes, int n_in,
                              void* d_out, int out_size) {
    const float* x        = (const float*)d_in[0];
    const int*   edge_row = (const int*)d_in[1];
    const int*   edge_col = (const int*)d_in[2];
    const float* edge_val = (const float*)d_in[3];
    const float* weights  = (const float*)d_in[4];
    const float* biases   = (const float*)d_in[5];
    float*       out      = (float*)d_out;

    int E = in_sizes[1];

    static bool attr_set = false;
    if (!attr_set) {
        cudaFuncSetAttribute(cheb_gemm_mma,
                             cudaFuncAttributeMaxDynamicSharedMemorySize,
                             32768);
        attr_set = true;
    }

    int histBlocks = (E + 255) / 256;
    int wprepBlocks = (KCHEB * COUT * 64 + 255) / 256;

    zero_hist_kernel<<<(VPAD + 255) / 256, 256>>>();
    prep1_kernel<<<TB_TOTAL + histBlocks, 256>>>(x, edge_row, E);
    scan_kernel<<<1, 1024>>>();
    prep2_kernel<<<histBlocks + wprepBlocks, 256>>>(edge_row, edge_col, edge_val, E,
                                                    weights, histBlocks);

    // Chebyshev recurrence
    {
        dim3 gb((V + 7) / 8, 2);
        spmm_cheb_kernel<<<gb, 256>>>(0, 0, 1, 1.f, 0.f);
        spmm_cheb_kernel<<<gb, 256>>>(1, 0, 2, 2.f, -1.f);
        spmm_cheb_kernel<<<gb, 256>>>(2, 1, 3, 2.f, -1.f);
    }

    // fp16 mma GEMM + bias + output permute
    {
        dim3 gb((V + 127) / 128, BDIM);
        cheb_gemm_mma<<<gb, 256, 32768>>>(biases, out);
    }
}